// round 8
// baseline (speedup 1.0000x reference)
#include <cuda_runtime.h>
#include <cuda_bf16.h>
#include <stdint.h>
#include <math.h>

// Problem constants
#define BB 4
#define CC 256
#define HH 80
#define WW 80
#define KK9 9
#define HW (HH*WW)
#define NPOS (BB*HW)             // 25600
#define NKB 36                   // K chunks: 9 taps x 4 chunks of 64 channels

// Scratch (device globals; no allocation allowed)
__device__ __align__(16) float g_xp[NPOS*CC];         // pooled input NHWC
__device__ __align__(16) float g_tmp[NPOS*CC];        // horizontal pool sums (NCHW)
__device__ __align__(16) float g_om[NPOS*32];         // per-pos offsets(18)+mask(9)
__device__ __align__(16) uint2 g_wf[NKB*8*32*32];     // deform W B-frags [kb][bsel][ntile][lane]
__device__ __align__(16) uint2 g_wfo[NKB*8*4*32];     // offmask W B-frags [kb][bsel][ntile(4)][lane]

// ============================ helpers ============================
__device__ __forceinline__ uint32_t smem_u32(const void* p) {
    uint32_t a;
    asm("{ .reg .u64 t; cvta.to.shared.u64 t, %1; cvt.u32.u64 %0, t; }" : "=r"(a) : "l"(p));
    return a;
}

__device__ __forceinline__ void ldsm4(uint32_t& a0, uint32_t& a1, uint32_t& a2,
                                      uint32_t& a3, uint32_t addr) {
    asm volatile("ldmatrix.sync.aligned.m8n8.x4.shared.b16 {%0,%1,%2,%3}, [%4];"
        : "=r"(a0), "=r"(a1), "=r"(a2), "=r"(a3) : "r"(addr));
}

__device__ __forceinline__ void mma16816(float* d, uint32_t a0, uint32_t a1,
                                         uint32_t a2, uint32_t a3,
                                         uint32_t b0, uint32_t b1) {
    asm volatile("mma.sync.aligned.m16n8k16.row.col.f32.bf16.bf16.f32 "
        "{%0,%1,%2,%3}, {%4,%5,%6,%7}, {%8,%9}, {%0,%1,%2,%3};"
        : "+f"(d[0]), "+f"(d[1]), "+f"(d[2]), "+f"(d[3])
        : "r"(a0), "r"(a1), "r"(a2), "r"(a3), "r"(b0), "r"(b1));
}

__device__ __forceinline__ uint32_t pack_bf16(float lo_k, float hi_k) {
    __nv_bfloat16 a = __float2bfloat16_rn(lo_k);
    __nv_bfloat16 b = __float2bfloat16_rn(hi_k);
    return ((uint32_t)__bfloat16_as_ushort(b) << 16) | __bfloat16_as_ushort(a);
}

// ---------------------------------------------------------------------------
// Kernel 1a: horizontal 3-sum (NCHW -> g_tmp NCHW)
// ---------------------------------------------------------------------------
__global__ void pool_h(const float* __restrict__ x) {
    int i = blockIdx.x * 256 + threadIdx.x;
    int w = i % WW;
    float s = x[i];
    if (w > 0)      s += x[i-1];
    if (w < WW-1)   s += x[i+1];
    g_tmp[i] = s;
}

// ---------------------------------------------------------------------------
// Kernel 1b: vertical 3-sum + /9 + transpose to NHWC (g_tmp -> g_xp)
// ---------------------------------------------------------------------------
__global__ void pool_v() {
    __shared__ float tile[16][17];
    int id = blockIdx.x;
    int c0 = (id & 15) * 16; id >>= 4;
    int w0 = (id % 5) * 16;  id /= 5;
    int h  = id % HH;
    int b  = id / HH;
    int t  = threadIdx.x;
    int ci = t >> 4, wi = t & 15;
    int c = c0 + ci, wcol = w0 + wi;
    const float* xb = g_tmp + (b*CC + c) * HW;
    float s = 0.f;
#pragma unroll
    for (int dy = -1; dy <= 1; dy++) {
        int y = h + dy;
        if (y < 0 || y >= HH) continue;
        s += xb[y*WW + wcol];
    }
    tile[ci][wi] = s * (1.f/9.f);
    __syncthreads();
    int wi2 = t >> 4, ci2 = t & 15;
    g_xp[((b*HH + h)*WW + w0 + wi2)*CC + c0 + ci2] = tile[ci2][wi2];
}

// ---------------------------------------------------------------------------
// Kernel 2: weight prep — B fragments for mma.m16n8k16.row.col (hi/lo split)
// ---------------------------------------------------------------------------
#define NWF  (NKB*8*32*32)       // 294912 uint2 records
#define NWFO (NKB*8*4*32)        // 36864 uint2 records
__global__ void wprep_kernel(const float* __restrict__ off_w,
                             const float* __restrict__ mod_w,
                             const float* __restrict__ w) {
    int i = blockIdx.x * 256 + threadIdx.x;
    if (i < NWF) {
        int j = i;
        int lane = j & 31;
        int nt   = (j >> 5) & 31;
        int bsel = (j >> 10) & 7;
        int kb   = j >> 13;
        int kk = kb >> 2;
        int lo = bsel >> 2;
        int o  = nt*8 + (lane >> 2);
        int c0 = (kb & 3)*64 + (bsel & 3)*16 + 2*(lane & 3);
        float wv[4];
#pragma unroll
        for (int q = 0; q < 4; q++) {
            int c = c0 + (q >> 1)*8 + (q & 1);
            float f = w[(o*CC + c)*KK9 + kk];
            __nv_bfloat16 h = __float2bfloat16_rn(f);
            wv[q] = lo ? (f - __bfloat162float(h)) : f;
        }
        uint2 rec;
        rec.x = pack_bf16(wv[0], wv[1]);
        rec.y = pack_bf16(wv[2], wv[3]);
        g_wf[j] = rec;
    } else if (i < NWF + NWFO) {
        int j = i - NWF;
        int lane = j & 31;
        int nt   = (j >> 5) & 3;
        int bsel = (j >> 7) & 7;
        int kb   = j >> 10;
        int kk = kb >> 2;
        int lo = bsel >> 2;
        int o  = nt*8 + (lane >> 2);
        int c0 = (kb & 3)*64 + (bsel & 3)*16 + 2*(lane & 3);
        float wv[4];
#pragma unroll
        for (int q = 0; q < 4; q++) {
            int c = c0 + (q >> 1)*8 + (q & 1);
            float f = 0.f;
            if (o < 18)      f = off_w[(o*CC + c)*KK9 + kk];
            else if (o < 27) f = mod_w[((o-18)*CC + c)*KK9 + kk];
            __nv_bfloat16 h = __float2bfloat16_rn(f);
            wv[q] = lo ? (f - __bfloat162float(h)) : f;
        }
        uint2 rec;
        rec.x = pack_bf16(wv[0], wv[1]);
        rec.y = pack_bf16(wv[2], wv[3]);
        g_wfo[j] = rec;
    }
}

// ---------------------------------------------------------------------------
// Kernel 3: offset+mask conv via mma.sync bf16 (3-term hi/lo split).
// Block: 256 thr = 8 warps (2m x 4n). M=32 pos, N=32(27). Grid 800.
// Unified 8-step loop with B-fragment register prefetch.
// ---------------------------------------------------------------------------
__device__ __forceinline__ void om_gather(char* sA, const int* sBase, int kb,
                                          int buf, int t) {
    const float4* xp4 = (const float4*)g_xp;
    int kk = kb >> 2;
    int p = t >> 3, g = t & 7;          // 256 tasks: 32 pos x 8 groups of 8 ch
    int bi = sBase[kk*32 + p];
    int fbase = (kb & 3)*16 + g*2;
    float v[8];
#pragma unroll
    for (int j = 0; j < 2; j++) {
        float4 a = make_float4(0.f, 0.f, 0.f, 0.f);
        if (bi >= 0) a = xp4[bi + fbase + j];
        v[4*j+0] = a.x; v[4*j+1] = a.y; v[4*j+2] = a.z; v[4*j+3] = a.w;
    }
    uint32_t hp[4], lp[4];
#pragma unroll
    for (int q = 0; q < 4; q++) {
        float a0 = v[2*q], a1 = v[2*q+1];
        __nv_bfloat16 h0 = __float2bfloat16_rn(a0);
        __nv_bfloat16 h1 = __float2bfloat16_rn(a1);
        hp[q] = ((uint32_t)__bfloat16_as_ushort(h1) << 16) | __bfloat16_as_ushort(h0);
        lp[q] = pack_bf16(a0 - __bfloat162float(h0), a1 - __bfloat162float(h1));
    }
    int off = p*128 + ((g*16) ^ ((p & 7) << 4));
    *(uint4*)(sA + buf*8192 + off)        = make_uint4(hp[0], hp[1], hp[2], hp[3]);
    *(uint4*)(sA + buf*8192 + 4096 + off) = make_uint4(lp[0], lp[1], lp[2], lp[3]);
}

__global__ void __launch_bounds__(256) offmask_kernel(const float* __restrict__ off_b,
                                                      const float* __restrict__ mod_b) {
    __shared__ __align__(16) char sA[2*8192];
    __shared__ int sBase[288];
    uint32_t sb = smem_u32(sA);

    int t = threadIdx.x, lane = t & 31, wid = t >> 5;
    int wm = wid >> 2, wn = wid & 3;       // 2m x 4n
    int pbase = blockIdx.x * 32;

    for (int q = t; q < 288; q += 256) {
        int tap = q >> 5, p = q & 31;
        int pgl = pbase + p;
        int b = pgl / HW, r = pgl % HW;
        int h = r / WW, w = r % WW;
        int y = h - 1 + tap/3, x = w - 1 + tap%3;
        sBase[q] = (((unsigned)y < HH) && ((unsigned)x < WW))
                   ? ((b*HH + y)*WW + x)*(CC/4) : -1;
    }
    __syncthreads();

    om_gather(sA, sBase, 0, 0, t);
    __syncthreads();

    float acc[4] = {0.f, 0.f, 0.f, 0.f};

    int rowterm = (wm*16 + (lane & 15)) * 128;
    int kterm = ((lane >> 4) & 1) * 16;
    int swzl = (lane & 7) << 4;

    for (int kb = 0; kb < NKB; kb++) {
        int buf = kb & 1;
        if (kb + 1 < NKB) om_gather(sA, sBase, kb + 1, buf ^ 1, t);

        uint32_t Ah = sb + buf*8192;
        uint32_t Al = Ah + 4096;
        const uint2* gb = g_wfo + (size_t)kb*8*4*32 + wn*32 + lane;

        uint2 bfc = gb[0];
#pragma unroll 1
        for (int s = 0; s < 8; s++) {
            uint2 bfn = gb[(((s + 1) & 7) * 4) * 32];
            int off = ((s & 3)*32 + kterm) ^ swzl;
            uint32_t a0, a1, a2, a3;
            ldsm4(a0, a1, a2, a3, Ah + rowterm + off);
            mma16816(acc, a0, a1, a2, a3, bfc.x, bfc.y);
            if (s < 4) {
                ldsm4(a0, a1, a2, a3, Al + rowterm + off);
                mma16816(acc, a0, a1, a2, a3, bfc.x, bfc.y);
            }
            bfc = bfn;
        }
        __syncthreads();
    }

    // epilogue: bias / 2*sigmoid, direct stores to g_om
    int row = pbase + wm*16 + (lane >> 2);
    int col = wn*8 + 2*(lane & 3);
#pragma unroll
    for (int q = 0; q < 4; q++) {
        int cc = col + (q & 1);
        int rr = row + (q >> 1)*8;
        float v = acc[q];
        if (cc < 18)      v = v + off_b[cc];
        else if (cc < 27) v = 2.f / (1.f + expf(-(v + mod_b[cc-18])));
        else continue;
        g_om[rr*32 + cc] = v;
    }
}

// ---------------------------------------------------------------------------
// Kernel 4: deformable conv via mma.sync bf16 (3-term hi/lo split).
// Block: 512 thr = 16 warps (4m x 4n), M=64 pos, N=256. Grid 400.
// Unified 8-step loop with B-fragment register prefetch (next step's 8 frags
// load while current step's 8-12 MMAs execute).
// ---------------------------------------------------------------------------
// dynamic smem layout (bytes)
#define DSM_A    0        // union: A bufs 2x(8192 hi + 8192 lo) = 32768  /  epi 65536
#define DSM_CW   65536    // float4[9][64]  = 9216
#define DSM_CI   74752    // int4[9][64]    = 9216
#define DSM_OB   83968    // int[64]
#define DSM_BIAS 84224    // float[256]
#define DSM_TOT  85248

__device__ __forceinline__ void deform_gather(char* dsm, int pbase, int kb, int buf,
                                              int t) {
    const float4* xp4 = (const float4*)g_xp;
    const float4* sCW = (const float4*)(dsm + DSM_CW);
    const int4*   sCI = (const int4*)(dsm + DSM_CI);
    int kk = kb >> 2;
    int p = t >> 3, g = t & 7;          // 512 tasks: 64 pos x 8 groups of 8 ch
    float4 bw = sCW[kk*64 + p];
    int4 iv = sCI[kk*64 + p];
    float v[8];
    int fbase = (kb & 3)*16 + g*2;
#pragma unroll
    for (int j = 0; j < 2; j++) {
        int f = fbase + j;
        float4 a  = xp4[iv.x + f];
        float4 b2 = xp4[iv.y + f];
        float4 c2 = xp4[iv.z + f];
        float4 d2 = xp4[iv.w + f];
        v[4*j+0] = bw.x*a.x + bw.y*b2.x + bw.z*c2.x + bw.w*d2.x;
        v[4*j+1] = bw.x*a.y + bw.y*b2.y + bw.z*c2.y + bw.w*d2.y;
        v[4*j+2] = bw.x*a.z + bw.y*b2.z + bw.z*c2.z + bw.w*d2.z;
        v[4*j+3] = bw.x*a.w + bw.y*b2.w + bw.z*c2.w + bw.w*d2.w;
    }
    uint32_t hp[4], lp[4];
#pragma unroll
    for (int q = 0; q < 4; q++) {
        float a0 = v[2*q], a1 = v[2*q+1];
        __nv_bfloat16 h0 = __float2bfloat16_rn(a0);
        __nv_bfloat16 h1 = __float2bfloat16_rn(a1);
        hp[q] = ((uint32_t)__bfloat16_as_ushort(h1) << 16) | __bfloat16_as_ushort(h0);
        lp[q] = pack_bf16(a0 - __bfloat162float(h0), a1 - __bfloat162float(h1));
    }
    char* Ab = dsm + DSM_A + buf*16384;
    int off = p*128 + ((g*16) ^ ((p & 7) << 4));   // SW128 swizzle
    *(uint4*)(Ab + off)        = make_uint4(hp[0], hp[1], hp[2], hp[3]);
    *(uint4*)(Ab + 8192 + off) = make_uint4(lp[0], lp[1], lp[2], lp[3]);
}

__global__ void __launch_bounds__(512, 1) deform_kernel(const float* __restrict__ bias,
                                                        float* __restrict__ out) {
    extern __shared__ __align__(16) char dsm[];
    float4* sCW = (float4*)(dsm + DSM_CW);
    int4*   sCI = (int4*)(dsm + DSM_CI);
    int*    sOB = (int*)(dsm + DSM_OB);
    float*  sBias = (float*)(dsm + DSM_BIAS);
    uint32_t sb = smem_u32(dsm);

    int t = threadIdx.x, lane = t & 31, wid = t >> 5;
    int wm = wid >> 2, wn = wid & 3;    // 4m x 4n
    int pbase = blockIdx.x * 64;

    // corners for all 9 taps
    for (int q = t; q < 576; q += 512) {
        int tap = q >> 6, p = q & 63;
        int pgl = pbase + p;
        int b = pgl / HW, r = pgl % HW;
        int h = r / WW, w = r % WW;
        float dy = g_om[pgl*32 + 2*tap];
        float dx = g_om[pgl*32 + 2*tap + 1];
        float m  = g_om[pgl*32 + 18 + tap];
        float py = (float)(h - 1 + tap/3) + dy;
        float px = (float)(w - 1 + tap%3) + dx;
        float fy = floorf(py), fx = floorf(px);
        int y0 = (int)fy, x0 = (int)fx;
        float wy = py - fy, wx = px - fx;
        int y1 = y0 + 1, x1 = x0 + 1;
        bool vy0 = (unsigned)y0 < HH, vy1 = (unsigned)y1 < HH;
        bool vx0 = (unsigned)x0 < WW, vx1 = (unsigned)x1 < WW;
        float4 wv;
        wv.x = (1.f-wy)*(1.f-wx)*m * (float)(vy0 && vx0);
        wv.y = (1.f-wy)*wx      *m * (float)(vy0 && vx1);
        wv.z = wy*(1.f-wx)      *m * (float)(vy1 && vx0);
        wv.w = wy*wx            *m * (float)(vy1 && vx1);
        int yc0 = min(max(y0, 0), HH-1), yc1 = min(max(y1, 0), HH-1);
        int xc0 = min(max(x0, 0), WW-1), xc1 = min(max(x1, 0), WW-1);
        int rowb = b*HH;
        int4 iv;
        iv.x = ((rowb + yc0)*WW + xc0) * (CC/4);
        iv.y = ((rowb + yc0)*WW + xc1) * (CC/4);
        iv.z = ((rowb + yc1)*WW + xc0) * (CC/4);
        iv.w = ((rowb + yc1)*WW + xc1) * (CC/4);
        sCW[q] = wv;
        sCI[q] = iv;
    }
    if (t < 64) {
        int pgl = pbase + t;
        sOB[t] = (pgl / HW) * (CC*HW) + (pgl % HW);
    }
    if (t < 256) sBias[t] = bias[t];
    __syncthreads();

    deform_gather(dsm, pbase, 0, 0, t);
    __syncthreads();

    float acc[8][4];
#pragma unroll
    for (int nt = 0; nt < 8; nt++)
#pragma unroll
        for (int q = 0; q < 4; q++) acc[nt][q] = 0.f;

    int m0 = wm * 16;
    int rowterm = (m0 + (lane & 15)) * 128;
    int kterm = ((lane >> 4) & 1) * 16;
    int swzl = (lane & 7) << 4;

    for (int kb = 0; kb < NKB; kb++) {
        int buf = kb & 1;
        if (kb + 1 < NKB) deform_gather(dsm, pbase, kb + 1, buf ^ 1, t);

        uint32_t Ah = sb + DSM_A + buf*16384;
        uint32_t Al = Ah + 8192;
        const uint2* gbase = g_wf + ((size_t)kb*8*32 + wn*8) * 32 + lane;

        uint2 bfc[8];
#pragma unroll
        for (int nt = 0; nt < 8; nt++) bfc[nt] = gbase[nt * 32];

#pragma unroll 1
        for (int s = 0; s < 8; s++) {
            uint2 bfn[8];
            int sp = (s + 1) & 7;
#pragma unroll
            for (int nt = 0; nt < 8; nt++)
                bfn[nt] = gbase[(sp*32 + nt) * 32];

            int off = ((s & 3)*32 + kterm) ^ swzl;
            uint32_t a0, a1, a2, a3;
            ldsm4(a0, a1, a2, a3, Ah + rowterm + off);
#pragma unroll
            for (int nt = 0; nt < 8; nt++)
                mma16816(acc[nt], a0, a1, a2, a3, bfc[nt].x, bfc[nt].y);
            if (s < 4) {
                ldsm4(a0, a1, a2, a3, Al + rowterm + off);
#pragma unroll
                for (int nt = 0; nt < 8; nt++)
                    mma16816(acc[nt], a0, a1, a2, a3, bfc[nt].x, bfc[nt].y);
            }
#pragma unroll
            for (int nt = 0; nt < 8; nt++) bfc[nt] = bfn[nt];
        }
        __syncthreads();
    }

    // epilogue: acc -> smem (reuse A region) -> coalesced NCHW stores
    float* sEp = (float*)(dsm + DSM_A);   // [o][m] = [256][64]
    int n0 = wn * 64;
    int rr = lane >> 2, cc = 2*(lane & 3);
#pragma unroll
    for (int nt = 0; nt < 8; nt++) {
        int n = n0 + nt*8 + cc;
        int m = m0 + rr;
        sEp[n*64 + m]         = acc[nt][0];
        sEp[(n+1)*64 + m]     = acc[nt][1];
        sEp[n*64 + m + 8]     = acc[nt][2];
        sEp[(n+1)*64 + m + 8] = acc[nt][3];
    }
    __syncthreads();
#pragma unroll
    for (int i = 0; i < 32; i++) {
        int idx = i*512 + t;
        int m = idx & 63, o = idx >> 6;
        out[sOB[m] + o*HW] = sEp[idx] + sBias[o];
    }
}

// ---------------------------------------------------------------------------
extern "C" void kernel_launch(void* const* d_in, const int* in_sizes, int n_in,
                              void* d_out, int out_size) {
    const float* x     = (const float*)d_in[0];
    const float* off_w = (const float*)d_in[1];
    const float* off_b = (const float*)d_in[2];
    const float* mod_w = (const float*)d_in[3];
    const float* mod_b = (const float*)d_in[4];
    const float* w     = (const float*)d_in[5];
    const float* b     = (const float*)d_in[6];
    float* out = (float*)d_out;

    cudaFuncSetAttribute(deform_kernel,
                         cudaFuncAttributeMaxDynamicSharedMemorySize, DSM_TOT);

    pool_h<<<(NPOS*CC)/256, 256>>>(x);
    pool_v<<<BB*HH*5*16, 256>>>();
    wprep_kernel<<<(NWF + NWFO + 255)/256, 256>>>(off_w, mod_w, w);
    offmask_kernel<<<NPOS/32, 256>>>(off_b, mod_b);
    deform_kernel<<<NPOS/64, 512, DSM_TOT>>>(b, out);
}

// round 9
// speedup vs baseline: 1.1713x; 1.1713x over previous
#include <cuda_runtime.h>
#include <cuda_bf16.h>
#include <stdint.h>
#include <math.h>

// Problem constants
#define BB 4
#define CC 256
#define HH 80
#define WW 80
#define KK9 9
#define HW (HH*WW)
#define NPOS (BB*HW)             // 25600
#define NKB 36                   // K chunks: 9 taps x 4 chunks of 64 channels

// Scratch (device globals; no allocation allowed)
__device__ __align__(16) float g_xp[NPOS*CC];         // pooled input NHWC
__device__ __align__(16) float g_tmp[NPOS*CC];        // horizontal pool sums (NCHW)
__device__ __align__(16) float g_om[NPOS*32];         // per-pos offsets(18)+mask(9)
__device__ __align__(16) uint2 g_wf[NKB*8*32*32];     // deform W B-frags [kb][bsel][ntile][lane]
__device__ __align__(16) uint2 g_wfo[NKB*8*4*32];     // offmask W B-frags [kb][bsel][ntile(4)][lane]

// ============================ helpers ============================
__device__ __forceinline__ uint32_t smem_u32(const void* p) {
    uint32_t a;
    asm("{ .reg .u64 t; cvta.to.shared.u64 t, %1; cvt.u32.u64 %0, t; }" : "=r"(a) : "l"(p));
    return a;
}

__device__ __forceinline__ void ldsm4(uint32_t& a0, uint32_t& a1, uint32_t& a2,
                                      uint32_t& a3, uint32_t addr) {
    asm volatile("ldmatrix.sync.aligned.m8n8.x4.shared.b16 {%0,%1,%2,%3}, [%4];"
        : "=r"(a0), "=r"(a1), "=r"(a2), "=r"(a3) : "r"(addr));
}

__device__ __forceinline__ void mma16816(float* d, uint32_t a0, uint32_t a1,
                                         uint32_t a2, uint32_t a3,
                                         uint32_t b0, uint32_t b1) {
    asm volatile("mma.sync.aligned.m16n8k16.row.col.f32.bf16.bf16.f32 "
        "{%0,%1,%2,%3}, {%4,%5,%6,%7}, {%8,%9}, {%0,%1,%2,%3};"
        : "+f"(d[0]), "+f"(d[1]), "+f"(d[2]), "+f"(d[3])
        : "r"(a0), "r"(a1), "r"(a2), "r"(a3), "r"(b0), "r"(b1));
}

__device__ __forceinline__ uint32_t pack_bf16(float lo_k, float hi_k) {
    __nv_bfloat16 a = __float2bfloat16_rn(lo_k);
    __nv_bfloat16 b = __float2bfloat16_rn(hi_k);
    return ((uint32_t)__bfloat16_as_ushort(b) << 16) | __bfloat16_as_ushort(a);
}

// ---------------------------------------------------------------------------
// Kernel 1a: horizontal 3-sum (NCHW -> g_tmp NCHW)
// ---------------------------------------------------------------------------
__global__ void pool_h(const float* __restrict__ x) {
    int i = blockIdx.x * 256 + threadIdx.x;
    int w = i % WW;
    float s = x[i];
    if (w > 0)      s += x[i-1];
    if (w < WW-1)   s += x[i+1];
    g_tmp[i] = s;
}

// ---------------------------------------------------------------------------
// Kernel 1b: vertical 3-sum + /9 + transpose to NHWC (g_tmp -> g_xp)
// ---------------------------------------------------------------------------
__global__ void pool_v() {
    __shared__ float tile[16][17];
    int id = blockIdx.x;
    int c0 = (id & 15) * 16; id >>= 4;
    int w0 = (id % 5) * 16;  id /= 5;
    int h  = id % HH;
    int b  = id / HH;
    int t  = threadIdx.x;
    int ci = t >> 4, wi = t & 15;
    int c = c0 + ci, wcol = w0 + wi;
    const float* xb = g_tmp + (b*CC + c) * HW;
    float s = 0.f;
#pragma unroll
    for (int dy = -1; dy <= 1; dy++) {
        int y = h + dy;
        if (y < 0 || y >= HH) continue;
        s += xb[y*WW + wcol];
    }
    tile[ci][wi] = s * (1.f/9.f);
    __syncthreads();
    int wi2 = t >> 4, ci2 = t & 15;
    g_xp[((b*HH + h)*WW + w0 + wi2)*CC + c0 + ci2] = tile[ci2][wi2];
}

// ---------------------------------------------------------------------------
// Kernel 2: weight prep — B fragments for mma.m16n8k16.row.col (hi/lo split)
// ---------------------------------------------------------------------------
#define NWF  (NKB*8*32*32)       // 294912 uint2 records
#define NWFO (NKB*8*4*32)        // 36864 uint2 records
__global__ void wprep_kernel(const float* __restrict__ off_w,
                             const float* __restrict__ mod_w,
                             const float* __restrict__ w) {
    int i = blockIdx.x * 256 + threadIdx.x;
    if (i < NWF) {
        int j = i;
        int lane = j & 31;
        int nt   = (j >> 5) & 31;
        int bsel = (j >> 10) & 7;
        int kb   = j >> 13;
        int kk = kb >> 2;
        int lo = bsel >> 2;
        int o  = nt*8 + (lane >> 2);
        int c0 = (kb & 3)*64 + (bsel & 3)*16 + 2*(lane & 3);
        float wv[4];
#pragma unroll
        for (int q = 0; q < 4; q++) {
            int c = c0 + (q >> 1)*8 + (q & 1);
            float f = w[(o*CC + c)*KK9 + kk];
            __nv_bfloat16 h = __float2bfloat16_rn(f);
            wv[q] = lo ? (f - __bfloat162float(h)) : f;
        }
        uint2 rec;
        rec.x = pack_bf16(wv[0], wv[1]);
        rec.y = pack_bf16(wv[2], wv[3]);
        g_wf[j] = rec;
    } else if (i < NWF + NWFO) {
        int j = i - NWF;
        int lane = j & 31;
        int nt   = (j >> 5) & 3;
        int bsel = (j >> 7) & 7;
        int kb   = j >> 10;
        int kk = kb >> 2;
        int lo = bsel >> 2;
        int o  = nt*8 + (lane >> 2);
        int c0 = (kb & 3)*64 + (bsel & 3)*16 + 2*(lane & 3);
        float wv[4];
#pragma unroll
        for (int q = 0; q < 4; q++) {
            int c = c0 + (q >> 1)*8 + (q & 1);
            float f = 0.f;
            if (o < 18)      f = off_w[(o*CC + c)*KK9 + kk];
            else if (o < 27) f = mod_w[((o-18)*CC + c)*KK9 + kk];
            __nv_bfloat16 h = __float2bfloat16_rn(f);
            wv[q] = lo ? (f - __bfloat162float(h)) : f;
        }
        uint2 rec;
        rec.x = pack_bf16(wv[0], wv[1]);
        rec.y = pack_bf16(wv[2], wv[3]);
        g_wfo[j] = rec;
    }
}

// ---------------------------------------------------------------------------
// Kernel 3: offset+mask conv via mma.sync bf16 (3-term hi/lo split).
// Block: 256 thr = 8 warps (2m x 4n). M=32 pos, N=32(27). Grid 800.
// (round-8 version — measured 125 us)
// ---------------------------------------------------------------------------
__device__ __forceinline__ void om_gather(char* sA, const int* sBase, int kb,
                                          int buf, int t) {
    const float4* xp4 = (const float4*)g_xp;
    int kk = kb >> 2;
    int p = t >> 3, g = t & 7;          // 256 tasks: 32 pos x 8 groups of 8 ch
    int bi = sBase[kk*32 + p];
    int fbase = (kb & 3)*16 + g*2;
    float v[8];
#pragma unroll
    for (int j = 0; j < 2; j++) {
        float4 a = make_float4(0.f, 0.f, 0.f, 0.f);
        if (bi >= 0) a = xp4[bi + fbase + j];
        v[4*j+0] = a.x; v[4*j+1] = a.y; v[4*j+2] = a.z; v[4*j+3] = a.w;
    }
    uint32_t hp[4], lp[4];
#pragma unroll
    for (int q = 0; q < 4; q++) {
        float a0 = v[2*q], a1 = v[2*q+1];
        __nv_bfloat16 h0 = __float2bfloat16_rn(a0);
        __nv_bfloat16 h1 = __float2bfloat16_rn(a1);
        hp[q] = ((uint32_t)__bfloat16_as_ushort(h1) << 16) | __bfloat16_as_ushort(h0);
        lp[q] = pack_bf16(a0 - __bfloat162float(h0), a1 - __bfloat162float(h1));
    }
    int off = p*128 + ((g*16) ^ ((p & 7) << 4));
    *(uint4*)(sA + buf*8192 + off)        = make_uint4(hp[0], hp[1], hp[2], hp[3]);
    *(uint4*)(sA + buf*8192 + 4096 + off) = make_uint4(lp[0], lp[1], lp[2], lp[3]);
}

__global__ void __launch_bounds__(256) offmask_kernel(const float* __restrict__ off_b,
                                                      const float* __restrict__ mod_b) {
    __shared__ __align__(16) char sA[2*8192];
    __shared__ int sBase[288];
    uint32_t sb = smem_u32(sA);

    int t = threadIdx.x, lane = t & 31, wid = t >> 5;
    int wm = wid >> 2, wn = wid & 3;       // 2m x 4n
    int pbase = blockIdx.x * 32;

    for (int q = t; q < 288; q += 256) {
        int tap = q >> 5, p = q & 31;
        int pgl = pbase + p;
        int b = pgl / HW, r = pgl % HW;
        int h = r / WW, w = r % WW;
        int y = h - 1 + tap/3, x = w - 1 + tap%3;
        sBase[q] = (((unsigned)y < HH) && ((unsigned)x < WW))
                   ? ((b*HH + y)*WW + x)*(CC/4) : -1;
    }
    __syncthreads();

    om_gather(sA, sBase, 0, 0, t);
    __syncthreads();

    float acc[4] = {0.f, 0.f, 0.f, 0.f};

    int rowterm = (wm*16 + (lane & 15)) * 128;
    int kterm = ((lane >> 4) & 1) * 16;
    int swzl = (lane & 7) << 4;

    for (int kb = 0; kb < NKB; kb++) {
        int buf = kb & 1;
        if (kb + 1 < NKB) om_gather(sA, sBase, kb + 1, buf ^ 1, t);

        uint32_t Ah = sb + buf*8192;
        uint32_t Al = Ah + 4096;
        const uint2* gb = g_wfo + (size_t)kb*8*4*32 + wn*32 + lane;

        uint2 bfc = gb[0];
#pragma unroll 1
        for (int s = 0; s < 8; s++) {
            uint2 bfn = gb[(((s + 1) & 7) * 4) * 32];
            int off = ((s & 3)*32 + kterm) ^ swzl;
            uint32_t a0, a1, a2, a3;
            ldsm4(a0, a1, a2, a3, Ah + rowterm + off);
            mma16816(acc, a0, a1, a2, a3, bfc.x, bfc.y);
            if (s < 4) {
                ldsm4(a0, a1, a2, a3, Al + rowterm + off);
                mma16816(acc, a0, a1, a2, a3, bfc.x, bfc.y);
            }
            bfc = bfn;
        }
        __syncthreads();
    }

    // epilogue: bias / 2*sigmoid, direct stores to g_om
    int row = pbase + wm*16 + (lane >> 2);
    int col = wn*8 + 2*(lane & 3);
#pragma unroll
    for (int q = 0; q < 4; q++) {
        int cc = col + (q & 1);
        int rr = row + (q >> 1)*8;
        float v = acc[q];
        if (cc < 18)      v = v + off_b[cc];
        else if (cc < 27) v = 2.f / (1.f + expf(-(v + mod_b[cc-18])));
        else continue;
        g_om[rr*32 + cc] = v;
    }
}

// ---------------------------------------------------------------------------
// Kernel 4: deformable conv via mma.sync bf16 (3-term hi/lo split).
// Block: 512 thr = 16 warps (4m x 4n), M=64 pos, N=256. Grid 400.
// (round-7 mainloop — measured inside the 516 us total; prefetch reverted)
// ---------------------------------------------------------------------------
// dynamic smem layout (bytes)
#define DSM_A    0        // union: A bufs 2x(8192 hi + 8192 lo) = 32768  /  epi 65536
#define DSM_CW   65536    // float4[9][64]  = 9216
#define DSM_CI   74752    // int4[9][64]    = 9216
#define DSM_OB   83968    // int[64]
#define DSM_BIAS 84224    // float[256]
#define DSM_TOT  85248

__device__ __forceinline__ void deform_gather(char* dsm, int pbase, int kb, int buf,
                                              int t) {
    const float4* xp4 = (const float4*)g_xp;
    const float4* sCW = (const float4*)(dsm + DSM_CW);
    const int4*   sCI = (const int4*)(dsm + DSM_CI);
    int kk = kb >> 2;
    int p = t >> 3, g = t & 7;          // 512 tasks: 64 pos x 8 groups of 8 ch
    float4 bw = sCW[kk*64 + p];
    int4 iv = sCI[kk*64 + p];
    float v[8];
    int fbase = (kb & 3)*16 + g*2;
#pragma unroll
    for (int j = 0; j < 2; j++) {
        int f = fbase + j;
        float4 a  = xp4[iv.x + f];
        float4 b2 = xp4[iv.y + f];
        float4 c2 = xp4[iv.z + f];
        float4 d2 = xp4[iv.w + f];
        v[4*j+0] = bw.x*a.x + bw.y*b2.x + bw.z*c2.x + bw.w*d2.x;
        v[4*j+1] = bw.x*a.y + bw.y*b2.y + bw.z*c2.y + bw.w*d2.y;
        v[4*j+2] = bw.x*a.z + bw.y*b2.z + bw.z*c2.z + bw.w*d2.z;
        v[4*j+3] = bw.x*a.w + bw.y*b2.w + bw.z*c2.w + bw.w*d2.w;
    }
    uint32_t hp[4], lp[4];
#pragma unroll
    for (int q = 0; q < 4; q++) {
        float a0 = v[2*q], a1 = v[2*q+1];
        __nv_bfloat16 h0 = __float2bfloat16_rn(a0);
        __nv_bfloat16 h1 = __float2bfloat16_rn(a1);
        hp[q] = ((uint32_t)__bfloat16_as_ushort(h1) << 16) | __bfloat16_as_ushort(h0);
        lp[q] = pack_bf16(a0 - __bfloat162float(h0), a1 - __bfloat162float(h1));
    }
    char* Ab = dsm + DSM_A + buf*16384;
    int off = p*128 + ((g*16) ^ ((p & 7) << 4));   // SW128 swizzle
    *(uint4*)(Ab + off)        = make_uint4(hp[0], hp[1], hp[2], hp[3]);
    *(uint4*)(Ab + 8192 + off) = make_uint4(lp[0], lp[1], lp[2], lp[3]);
}

__global__ void __launch_bounds__(512, 1) deform_kernel(const float* __restrict__ bias,
                                                        float* __restrict__ out) {
    extern __shared__ __align__(16) char dsm[];
    float4* sCW = (float4*)(dsm + DSM_CW);
    int4*   sCI = (int4*)(dsm + DSM_CI);
    int*    sOB = (int*)(dsm + DSM_OB);
    float*  sBias = (float*)(dsm + DSM_BIAS);
    uint32_t sb = smem_u32(dsm);

    int t = threadIdx.x, lane = t & 31, wid = t >> 5;
    int wm = wid >> 2, wn = wid & 3;    // 4m x 4n
    int pbase = blockIdx.x * 64;

    // corners for all 9 taps
    for (int q = t; q < 576; q += 512) {
        int tap = q >> 6, p = q & 63;
        int pgl = pbase + p;
        int b = pgl / HW, r = pgl % HW;
        int h = r / WW, w = r % WW;
        float dy = g_om[pgl*32 + 2*tap];
        float dx = g_om[pgl*32 + 2*tap + 1];
        float m  = g_om[pgl*32 + 18 + tap];
        float py = (float)(h - 1 + tap/3) + dy;
        float px = (float)(w - 1 + tap%3) + dx;
        float fy = floorf(py), fx = floorf(px);
        int y0 = (int)fy, x0 = (int)fx;
        float wy = py - fy, wx = px - fx;
        int y1 = y0 + 1, x1 = x0 + 1;
        bool vy0 = (unsigned)y0 < HH, vy1 = (unsigned)y1 < HH;
        bool vx0 = (unsigned)x0 < WW, vx1 = (unsigned)x1 < WW;
        float4 wv;
        wv.x = (1.f-wy)*(1.f-wx)*m * (float)(vy0 && vx0);
        wv.y = (1.f-wy)*wx      *m * (float)(vy0 && vx1);
        wv.z = wy*(1.f-wx)      *m * (float)(vy1 && vx0);
        wv.w = wy*wx            *m * (float)(vy1 && vx1);
        int yc0 = min(max(y0, 0), HH-1), yc1 = min(max(y1, 0), HH-1);
        int xc0 = min(max(x0, 0), WW-1), xc1 = min(max(x1, 0), WW-1);
        int rowb = b*HH;
        int4 iv;
        iv.x = ((rowb + yc0)*WW + xc0) * (CC/4);
        iv.y = ((rowb + yc0)*WW + xc1) * (CC/4);
        iv.z = ((rowb + yc1)*WW + xc0) * (CC/4);
        iv.w = ((rowb + yc1)*WW + xc1) * (CC/4);
        sCW[q] = wv;
        sCI[q] = iv;
    }
    if (t < 64) {
        int pgl = pbase + t;
        sOB[t] = (pgl / HW) * (CC*HW) + (pgl % HW);
    }
    if (t < 256) sBias[t] = bias[t];
    __syncthreads();

    deform_gather(dsm, pbase, 0, 0, t);
    __syncthreads();

    float acc[8][4];
#pragma unroll
    for (int nt = 0; nt < 8; nt++)
#pragma unroll
        for (int q = 0; q < 4; q++) acc[nt][q] = 0.f;

    int m0 = wm * 16;
    int rowterm = (m0 + (lane & 15)) * 128;
    int kterm = ((lane >> 4) & 1) * 16;
    int swzl = (lane & 7) << 4;

    for (int kb = 0; kb < NKB; kb++) {
        int buf = kb & 1;
        if (kb + 1 < NKB) deform_gather(dsm, pbase, kb + 1, buf ^ 1, t);

        uint32_t Ah = sb + DSM_A + buf*16384;
        uint32_t Al = Ah + 8192;
        const uint2* gbase = g_wf + ((size_t)kb*8*32 + wn*8) * 32 + lane;

        // hi-weight halves: A_hi and A_lo terms share B frags
#pragma unroll 1
        for (int h = 0; h < 4; h++) {
            uint2 bf[8];
#pragma unroll
            for (int nt = 0; nt < 8; nt++)
                bf[nt] = gbase[(h*32 + nt) * 32];
            int off = (h*32 + kterm) ^ swzl;
            uint32_t a0, a1, a2, a3;
            ldsm4(a0, a1, a2, a3, Ah + rowterm + off);
#pragma unroll
            for (int nt = 0; nt < 8; nt++)
                mma16816(acc[nt], a0, a1, a2, a3, bf[nt].x, bf[nt].y);
            ldsm4(a0, a1, a2, a3, Al + rowterm + off);
#pragma unroll
            for (int nt = 0; nt < 8; nt++)
                mma16816(acc[nt], a0, a1, a2, a3, bf[nt].x, bf[nt].y);
        }
        // lo-weight halves: A_hi only
#pragma unroll 1
        for (int h = 0; h < 4; h++) {
            uint2 bf[8];
#pragma unroll
            for (int nt = 0; nt < 8; nt++)
                bf[nt] = gbase[((4 + h)*32 + nt) * 32];
            int off = (h*32 + kterm) ^ swzl;
            uint32_t a0, a1, a2, a3;
            ldsm4(a0, a1, a2, a3, Ah + rowterm + off);
#pragma unroll
            for (int nt = 0; nt < 8; nt++)
                mma16816(acc[nt], a0, a1, a2, a3, bf[nt].x, bf[nt].y);
        }
        __syncthreads();
    }

    // epilogue: acc -> smem (reuse A region) -> coalesced NCHW stores
    float* sEp = (float*)(dsm + DSM_A);   // [o][m] = [256][64]
    int n0 = wn * 64;
    int rr = lane >> 2, cc = 2*(lane & 3);
#pragma unroll
    for (int nt = 0; nt < 8; nt++) {
        int n = n0 + nt*8 + cc;
        int m = m0 + rr;
        sEp[n*64 + m]         = acc[nt][0];
        sEp[(n+1)*64 + m]     = acc[nt][1];
        sEp[n*64 + m + 8]     = acc[nt][2];
        sEp[(n+1)*64 + m + 8] = acc[nt][3];
    }
    __syncthreads();
#pragma unroll
    for (int i = 0; i < 32; i++) {
        int idx = i*512 + t;
        int m = idx & 63, o = idx >> 6;
        out[sOB[m] + o*HW] = sEp[idx] + sBias[o];
    }
}

// ---------------------------------------------------------------------------
extern "C" void kernel_launch(void* const* d_in, const int* in_sizes, int n_in,
                              void* d_out, int out_size) {
    const float* x     = (const float*)d_in[0];
    const float* off_w = (const float*)d_in[1];
    const float* off_b = (const float*)d_in[2];
    const float* mod_w = (const float*)d_in[3];
    const float* mod_b = (const float*)d_in[4];
    const float* w     = (const float*)d_in[5];
    const float* b     = (const float*)d_in[6];
    float* out = (float*)d_out;

    cudaFuncSetAttribute(deform_kernel,
                         cudaFuncAttributeMaxDynamicSharedMemorySize, DSM_TOT);

    pool_h<<<(NPOS*CC)/256, 256>>>(x);
    pool_v<<<BB*HH*5*16, 256>>>();
    wprep_kernel<<<(NWF + NWFO + 255)/256, 256>>>(off_w, mod_w, w);
    offmask_kernel<<<NPOS/32, 256>>>(off_b, mod_b);
    deform_kernel<<<NPOS/64, 512, DSM_TOT>>>(b, out);
}

// round 10
// speedup vs baseline: 1.1802x; 1.0077x over previous
#include <cuda_runtime.h>
#include <cuda_bf16.h>
#include <stdint.h>
#include <math.h>

// Problem constants
#define BB 4
#define CC 256
#define HH 80
#define WW 80
#define KK9 9
#define HW (HH*WW)
#define NPOS (BB*HW)             // 25600
#define NKB 36                   // K chunks: 9 taps x 4 chunks of 64 channels

// Scratch (device globals; no allocation allowed)
__device__ __align__(16) float    g_xp[NPOS*CC];      // pooled input NHWC (fp32)
__device__ __align__(16) uint32_t g_xph[NPOS*CC/2];   // bf16 hi image, 2ch/u32
__device__ __align__(16) uint32_t g_xpl[NPOS*CC/2];   // bf16 lo residual image
__device__ __align__(16) float    g_tmp[NPOS*CC];     // horizontal pool sums (NCHW)
__device__ __align__(16) float    g_om[NPOS*32];      // per-pos offsets(18)+mask(9)
__device__ __align__(16) uint2 g_wf[NKB*8*32*32];     // deform W B-frags [kb][bsel][ntile][lane]
__device__ __align__(16) uint2 g_wfo[NKB*8*4*32];     // offmask W B-frags [kb][bsel][ntile(4)][lane]

// ============================ helpers ============================
__device__ __forceinline__ uint32_t smem_u32(const void* p) {
    uint32_t a;
    asm("{ .reg .u64 t; cvta.to.shared.u64 t, %1; cvt.u32.u64 %0, t; }" : "=r"(a) : "l"(p));
    return a;
}

__device__ __forceinline__ void ldsm4(uint32_t& a0, uint32_t& a1, uint32_t& a2,
                                      uint32_t& a3, uint32_t addr) {
    asm volatile("ldmatrix.sync.aligned.m8n8.x4.shared.b16 {%0,%1,%2,%3}, [%4];"
        : "=r"(a0), "=r"(a1), "=r"(a2), "=r"(a3) : "r"(addr));
}

__device__ __forceinline__ void mma16816(float* d, uint32_t a0, uint32_t a1,
                                         uint32_t a2, uint32_t a3,
                                         uint32_t b0, uint32_t b1) {
    asm volatile("mma.sync.aligned.m16n8k16.row.col.f32.bf16.bf16.f32 "
        "{%0,%1,%2,%3}, {%4,%5,%6,%7}, {%8,%9}, {%0,%1,%2,%3};"
        : "+f"(d[0]), "+f"(d[1]), "+f"(d[2]), "+f"(d[3])
        : "r"(a0), "r"(a1), "r"(a2), "r"(a3), "r"(b0), "r"(b1));
}

__device__ __forceinline__ uint32_t pack_bf16(float lo_k, float hi_k) {
    __nv_bfloat16 a = __float2bfloat16_rn(lo_k);
    __nv_bfloat16 b = __float2bfloat16_rn(hi_k);
    return ((uint32_t)__bfloat16_as_ushort(b) << 16) | __bfloat16_as_ushort(a);
}

// ---------------------------------------------------------------------------
// Kernel 1a: horizontal 3-sum (NCHW -> g_tmp NCHW)
// ---------------------------------------------------------------------------
__global__ void pool_h(const float* __restrict__ x) {
    int i = blockIdx.x * 256 + threadIdx.x;
    int w = i % WW;
    float s = x[i];
    if (w > 0)      s += x[i-1];
    if (w < WW-1)   s += x[i+1];
    g_tmp[i] = s;
}

// ---------------------------------------------------------------------------
// Kernel 1b: vertical 3-sum + /9 + transpose to NHWC (g_tmp -> g_xp)
// Also emits bf16 hi/lo images (g_xph/g_xpl), 2 channels packed per u32.
// ---------------------------------------------------------------------------
__global__ void pool_v() {
    __shared__ float tile[16][17];
    int id = blockIdx.x;
    int c0 = (id & 15) * 16; id >>= 4;
    int w0 = (id % 5) * 16;  id /= 5;
    int h  = id % HH;
    int b  = id / HH;
    int t  = threadIdx.x;
    int ci = t >> 4, wi = t & 15;
    int c = c0 + ci, wcol = w0 + wi;
    const float* xb = g_tmp + (b*CC + c) * HW;
    float s = 0.f;
#pragma unroll
    for (int dy = -1; dy <= 1; dy++) {
        int y = h + dy;
        if (y < 0 || y >= HH) continue;
        s += xb[y*WW + wcol];
    }
    tile[ci][wi] = s * (1.f/9.f);
    __syncthreads();
    int wi2 = t >> 4, ci2 = t & 15;
    int pos = (b*HH + h)*WW + w0 + wi2;
    float v0 = tile[ci2][wi2];
    g_xp[pos*CC + c0 + ci2] = v0;
    if ((ci2 & 1) == 0) {
        float v1 = tile[ci2+1][wi2];
        __nv_bfloat16 h0 = __float2bfloat16_rn(v0);
        __nv_bfloat16 h1 = __float2bfloat16_rn(v1);
        uint32_t hp = ((uint32_t)__bfloat16_as_ushort(h1) << 16)
                    | __bfloat16_as_ushort(h0);
        uint32_t lp = pack_bf16(v0 - __bfloat162float(h0),
                                v1 - __bfloat162float(h1));
        int idx = (pos*CC + c0 + ci2) >> 1;
        g_xph[idx] = hp;
        g_xpl[idx] = lp;
    }
}

// ---------------------------------------------------------------------------
// Kernel 2: weight prep — B fragments for mma.m16n8k16.row.col (hi/lo split)
// ---------------------------------------------------------------------------
#define NWF  (NKB*8*32*32)       // 294912 uint2 records
#define NWFO (NKB*8*4*32)        // 36864 uint2 records
__global__ void wprep_kernel(const float* __restrict__ off_w,
                             const float* __restrict__ mod_w,
                             const float* __restrict__ w) {
    int i = blockIdx.x * 256 + threadIdx.x;
    if (i < NWF) {
        int j = i;
        int lane = j & 31;
        int nt   = (j >> 5) & 31;
        int bsel = (j >> 10) & 7;
        int kb   = j >> 13;
        int kk = kb >> 2;
        int lo = bsel >> 2;
        int o  = nt*8 + (lane >> 2);
        int c0 = (kb & 3)*64 + (bsel & 3)*16 + 2*(lane & 3);
        float wv[4];
#pragma unroll
        for (int q = 0; q < 4; q++) {
            int c = c0 + (q >> 1)*8 + (q & 1);
            float f = w[(o*CC + c)*KK9 + kk];
            __nv_bfloat16 h = __float2bfloat16_rn(f);
            wv[q] = lo ? (f - __bfloat162float(h)) : f;
        }
        uint2 rec;
        rec.x = pack_bf16(wv[0], wv[1]);
        rec.y = pack_bf16(wv[2], wv[3]);
        g_wf[j] = rec;
    } else if (i < NWF + NWFO) {
        int j = i - NWF;
        int lane = j & 31;
        int nt   = (j >> 5) & 3;
        int bsel = (j >> 7) & 7;
        int kb   = j >> 10;
        int kk = kb >> 2;
        int lo = bsel >> 2;
        int o  = nt*8 + (lane >> 2);
        int c0 = (kb & 3)*64 + (bsel & 3)*16 + 2*(lane & 3);
        float wv[4];
#pragma unroll
        for (int q = 0; q < 4; q++) {
            int c = c0 + (q >> 1)*8 + (q & 1);
            float f = 0.f;
            if (o < 18)      f = off_w[(o*CC + c)*KK9 + kk];
            else if (o < 27) f = mod_w[((o-18)*CC + c)*KK9 + kk];
            __nv_bfloat16 h = __float2bfloat16_rn(f);
            wv[q] = lo ? (f - __bfloat162float(h)) : f;
        }
        uint2 rec;
        rec.x = pack_bf16(wv[0], wv[1]);
        rec.y = pack_bf16(wv[2], wv[3]);
        g_wfo[j] = rec;
    }
}

// ---------------------------------------------------------------------------
// Kernel 3: offset+mask conv via mma.sync bf16 (3-term hi/lo split).
// Block: 256 thr = 8 warps (2m x 4n). M=32 pos, N=32(27). Grid 800.
// Gather is now a pure swizzled copy from precomputed g_xph/g_xpl.
// ---------------------------------------------------------------------------
__device__ __forceinline__ void om_gather(char* sA, const int* sBase, int kb,
                                          int buf, int t) {
    const uint4* xph4 = (const uint4*)g_xph;
    const uint4* xpl4 = (const uint4*)g_xpl;
    int kk = kb >> 2;
    int p = t >> 3, g = t & 7;          // 256 tasks: 32 pos x 8 groups of 8 ch
    int pos = sBase[kk*32 + p];
    uint4 hp = make_uint4(0u, 0u, 0u, 0u);
    uint4 lp = hp;
    if (pos >= 0) {
        int idx = pos*32 + (kb & 3)*8 + g;   // uint4 units: CC/8 = 32 per pos
        hp = xph4[idx];
        lp = xpl4[idx];
    }
    int off = p*128 + ((g*16) ^ ((p & 7) << 4));
    *(uint4*)(sA + buf*8192 + off)        = hp;
    *(uint4*)(sA + buf*8192 + 4096 + off) = lp;
}

__global__ void __launch_bounds__(256) offmask_kernel(const float* __restrict__ off_b,
                                                      const float* __restrict__ mod_b) {
    __shared__ __align__(16) char sA[2*8192];
    __shared__ int sBase[288];
    uint32_t sb = smem_u32(sA);

    int t = threadIdx.x, lane = t & 31, wid = t >> 5;
    int wm = wid >> 2, wn = wid & 3;       // 2m x 4n
    int pbase = blockIdx.x * 32;

    for (int q = t; q < 288; q += 256) {
        int tap = q >> 5, p = q & 31;
        int pgl = pbase + p;
        int b = pgl / HW, r = pgl % HW;
        int h = r / WW, w = r % WW;
        int y = h - 1 + tap/3, x = w - 1 + tap%3;
        sBase[q] = (((unsigned)y < HH) && ((unsigned)x < WW))
                   ? ((b*HH + y)*WW + x) : -1;
    }
    __syncthreads();

    om_gather(sA, sBase, 0, 0, t);
    __syncthreads();

    float acc[4] = {0.f, 0.f, 0.f, 0.f};

    int rowterm = (wm*16 + (lane & 15)) * 128;
    int kterm = ((lane >> 4) & 1) * 16;
    int swzl = (lane & 7) << 4;

    for (int kb = 0; kb < NKB; kb++) {
        int buf = kb & 1;
        if (kb + 1 < NKB) om_gather(sA, sBase, kb + 1, buf ^ 1, t);

        uint32_t Ah = sb + buf*8192;
        uint32_t Al = Ah + 4096;
        const uint2* gb = g_wfo + (size_t)kb*8*4*32 + wn*32 + lane;

        uint2 bfc = gb[0];
#pragma unroll 1
        for (int s = 0; s < 8; s++) {
            uint2 bfn = gb[(((s + 1) & 7) * 4) * 32];
            int off = ((s & 3)*32 + kterm) ^ swzl;
            uint32_t a0, a1, a2, a3;
            ldsm4(a0, a1, a2, a3, Ah + rowterm + off);
            mma16816(acc, a0, a1, a2, a3, bfc.x, bfc.y);
            if (s < 4) {
                ldsm4(a0, a1, a2, a3, Al + rowterm + off);
                mma16816(acc, a0, a1, a2, a3, bfc.x, bfc.y);
            }
            bfc = bfn;
        }
        __syncthreads();
    }

    // epilogue: bias / 2*sigmoid, direct stores to g_om
    int row = pbase + wm*16 + (lane >> 2);
    int col = wn*8 + 2*(lane & 3);
#pragma unroll
    for (int q = 0; q < 4; q++) {
        int cc = col + (q & 1);
        int rr = row + (q >> 1)*8;
        float v = acc[q];
        if (cc < 18)      v = v + off_b[cc];
        else if (cc < 27) v = 2.f / (1.f + expf(-(v + mod_b[cc-18])));
        else continue;
        g_om[rr*32 + cc] = v;
    }
}

// ---------------------------------------------------------------------------
// Kernel 4: deformable conv via mma.sync bf16 (3-term hi/lo split).
// Block: 512 thr = 16 warps (4m x 4n), M=64 pos, N=256. Grid 400.
// (unchanged from the 516-us configuration)
// ---------------------------------------------------------------------------
// dynamic smem layout (bytes)
#define DSM_A    0        // union: A bufs 2x(8192 hi + 8192 lo) = 32768  /  epi 65536
#define DSM_CW   65536    // float4[9][64]  = 9216
#define DSM_CI   74752    // int4[9][64]    = 9216
#define DSM_OB   83968    // int[64]
#define DSM_BIAS 84224    // float[256]
#define DSM_TOT  85248

__device__ __forceinline__ void deform_gather(char* dsm, int pbase, int kb, int buf,
                                              int t) {
    const float4* xp4 = (const float4*)g_xp;
    const float4* sCW = (const float4*)(dsm + DSM_CW);
    const int4*   sCI = (const int4*)(dsm + DSM_CI);
    int kk = kb >> 2;
    int p = t >> 3, g = t & 7;          // 512 tasks: 64 pos x 8 groups of 8 ch
    float4 bw = sCW[kk*64 + p];
    int4 iv = sCI[kk*64 + p];
    float v[8];
    int fbase = (kb & 3)*16 + g*2;
#pragma unroll
    for (int j = 0; j < 2; j++) {
        int f = fbase + j;
        float4 a  = xp4[iv.x + f];
        float4 b2 = xp4[iv.y + f];
        float4 c2 = xp4[iv.z + f];
        float4 d2 = xp4[iv.w + f];
        v[4*j+0] = bw.x*a.x + bw.y*b2.x + bw.z*c2.x + bw.w*d2.x;
        v[4*j+1] = bw.x*a.y + bw.y*b2.y + bw.z*c2.y + bw.w*d2.y;
        v[4*j+2] = bw.x*a.z + bw.y*b2.z + bw.z*c2.z + bw.w*d2.z;
        v[4*j+3] = bw.x*a.w + bw.y*b2.w + bw.z*c2.w + bw.w*d2.w;
    }
    uint32_t hp[4], lp[4];
#pragma unroll
    for (int q = 0; q < 4; q++) {
        float a0 = v[2*q], a1 = v[2*q+1];
        __nv_bfloat16 h0 = __float2bfloat16_rn(a0);
        __nv_bfloat16 h1 = __float2bfloat16_rn(a1);
        hp[q] = ((uint32_t)__bfloat16_as_ushort(h1) << 16) | __bfloat16_as_ushort(h0);
        lp[q] = pack_bf16(a0 - __bfloat162float(h0), a1 - __bfloat162float(h1));
    }
    char* Ab = dsm + DSM_A + buf*16384;
    int off = p*128 + ((g*16) ^ ((p & 7) << 4));   // SW128 swizzle
    *(uint4*)(Ab + off)        = make_uint4(hp[0], hp[1], hp[2], hp[3]);
    *(uint4*)(Ab + 8192 + off) = make_uint4(lp[0], lp[1], lp[2], lp[3]);
}

__global__ void __launch_bounds__(512, 1) deform_kernel(const float* __restrict__ bias,
                                                        float* __restrict__ out) {
    extern __shared__ __align__(16) char dsm[];
    float4* sCW = (float4*)(dsm + DSM_CW);
    int4*   sCI = (int4*)(dsm + DSM_CI);
    int*    sOB = (int*)(dsm + DSM_OB);
    float*  sBias = (float*)(dsm + DSM_BIAS);
    uint32_t sb = smem_u32(dsm);

    int t = threadIdx.x, lane = t & 31, wid = t >> 5;
    int wm = wid >> 2, wn = wid & 3;    // 4m x 4n
    int pbase = blockIdx.x * 64;

    // corners for all 9 taps
    for (int q = t; q < 576; q += 512) {
        int tap = q >> 6, p = q & 63;
        int pgl = pbase + p;
        int b = pgl / HW, r = pgl % HW;
        int h = r / WW, w = r % WW;
        float dy = g_om[pgl*32 + 2*tap];
        float dx = g_om[pgl*32 + 2*tap + 1];
        float m  = g_om[pgl*32 + 18 + tap];
        float py = (float)(h - 1 + tap/3) + dy;
        float px = (float)(w - 1 + tap%3) + dx;
        float fy = floorf(py), fx = floorf(px);
        int y0 = (int)fy, x0 = (int)fx;
        float wy = py - fy, wx = px - fx;
        int y1 = y0 + 1, x1 = x0 + 1;
        bool vy0 = (unsigned)y0 < HH, vy1 = (unsigned)y1 < HH;
        bool vx0 = (unsigned)x0 < WW, vx1 = (unsigned)x1 < WW;
        float4 wv;
        wv.x = (1.f-wy)*(1.f-wx)*m * (float)(vy0 && vx0);
        wv.y = (1.f-wy)*wx      *m * (float)(vy0 && vx1);
        wv.z = wy*(1.f-wx)      *m * (float)(vy1 && vx0);
        wv.w = wy*wx            *m * (float)(vy1 && vx1);
        int yc0 = min(max(y0, 0), HH-1), yc1 = min(max(y1, 0), HH-1);
        int xc0 = min(max(x0, 0), WW-1), xc1 = min(max(x1, 0), WW-1);
        int rowb = b*HH;
        int4 iv;
        iv.x = ((rowb + yc0)*WW + xc0) * (CC/4);
        iv.y = ((rowb + yc0)*WW + xc1) * (CC/4);
        iv.z = ((rowb + yc1)*WW + xc0) * (CC/4);
        iv.w = ((rowb + yc1)*WW + xc1) * (CC/4);
        sCW[q] = wv;
        sCI[q] = iv;
    }
    if (t < 64) {
        int pgl = pbase + t;
        sOB[t] = (pgl / HW) * (CC*HW) + (pgl % HW);
    }
    if (t < 256) sBias[t] = bias[t];
    __syncthreads();

    deform_gather(dsm, pbase, 0, 0, t);
    __syncthreads();

    float acc[8][4];
#pragma unroll
    for (int nt = 0; nt < 8; nt++)
#pragma unroll
        for (int q = 0; q < 4; q++) acc[nt][q] = 0.f;

    int m0 = wm * 16;
    int rowterm = (m0 + (lane & 15)) * 128;
    int kterm = ((lane >> 4) & 1) * 16;
    int swzl = (lane & 7) << 4;

    for (int kb = 0; kb < NKB; kb++) {
        int buf = kb & 1;
        if (kb + 1 < NKB) deform_gather(dsm, pbase, kb + 1, buf ^ 1, t);

        uint32_t Ah = sb + DSM_A + buf*16384;
        uint32_t Al = Ah + 8192;
        const uint2* gbase = g_wf + ((size_t)kb*8*32 + wn*8) * 32 + lane;

        // hi-weight halves: A_hi and A_lo terms share B frags
#pragma unroll 1
        for (int h = 0; h < 4; h++) {
            uint2 bf[8];
#pragma unroll
            for (int nt = 0; nt < 8; nt++)
                bf[nt] = gbase[(h*32 + nt) * 32];
            int off = (h*32 + kterm) ^ swzl;
            uint32_t a0, a1, a2, a3;
            ldsm4(a0, a1, a2, a3, Ah + rowterm + off);
#pragma unroll
            for (int nt = 0; nt < 8; nt++)
                mma16816(acc[nt], a0, a1, a2, a3, bf[nt].x, bf[nt].y);
            ldsm4(a0, a1, a2, a3, Al + rowterm + off);
#pragma unroll
            for (int nt = 0; nt < 8; nt++)
                mma16816(acc[nt], a0, a1, a2, a3, bf[nt].x, bf[nt].y);
        }
        // lo-weight halves: A_hi only
#pragma unroll 1
        for (int h = 0; h < 4; h++) {
            uint2 bf[8];
#pragma unroll
            for (int nt = 0; nt < 8; nt++)
                bf[nt] = gbase[((4 + h)*32 + nt) * 32];
            int off = (h*32 + kterm) ^ swzl;
            uint32_t a0, a1, a2, a3;
            ldsm4(a0, a1, a2, a3, Ah + rowterm + off);
#pragma unroll
            for (int nt = 0; nt < 8; nt++)
                mma16816(acc[nt], a0, a1, a2, a3, bf[nt].x, bf[nt].y);
        }
        __syncthreads();
    }

    // epilogue: acc -> smem (reuse A region) -> coalesced NCHW stores
    float* sEp = (float*)(dsm + DSM_A);   // [o][m] = [256][64]
    int n0 = wn * 64;
    int rr = lane >> 2, cc = 2*(lane & 3);
#pragma unroll
    for (int nt = 0; nt < 8; nt++) {
        int n = n0 + nt*8 + cc;
        int m = m0 + rr;
        sEp[n*64 + m]         = acc[nt][0];
        sEp[(n+1)*64 + m]     = acc[nt][1];
        sEp[n*64 + m + 8]     = acc[nt][2];
        sEp[(n+1)*64 + m + 8] = acc[nt][3];
    }
    __syncthreads();
#pragma unroll
    for (int i = 0; i < 32; i++) {
        int idx = i*512 + t;
        int m = idx & 63, o = idx >> 6;
        out[sOB[m] + o*HW] = sEp[idx] + sBias[o];
    }
}

// ---------------------------------------------------------------------------
extern "C" void kernel_launch(void* const* d_in, const int* in_sizes, int n_in,
                              void* d_out, int out_size) {
    const float* x     = (const float*)d_in[0];
    const float* off_w = (const float*)d_in[1];
    const float* off_b = (const float*)d_in[2];
    const float* mod_w = (const float*)d_in[3];
    const float* mod_b = (const float*)d_in[4];
    const float* w     = (const float*)d_in[5];
    const float* b     = (const float*)d_in[6];
    float* out = (float*)d_out;

    cudaFuncSetAttribute(deform_kernel,
                         cudaFuncAttributeMaxDynamicSharedMemorySize, DSM_TOT);

    pool_h<<<(NPOS*CC)/256, 256>>>(x);
    pool_v<<<BB*HH*5*16, 256>>>();
    wprep_kernel<<<(NWF + NWFO + 255)/256, 256>>>(off_w, mod_w, w);
    offmask_kernel<<<NPOS/32, 256>>>(off_b, mod_b);
    deform_kernel<<<NPOS/64, 512, DSM_TOT>>>(b, out);
}

// round 11
// speedup vs baseline: 1.2446x; 1.0545x over previous
#include <cuda_runtime.h>
#include <cuda_bf16.h>
#include <stdint.h>
#include <math.h>

// Problem constants
#define BB 4
#define CC 256
#define HH 80
#define WW 80
#define KK9 9
#define HW (HH*WW)
#define NPOS (BB*HW)             // 25600
#define NKB 36                   // K chunks: 9 taps x 4 chunks of 64 channels

// Scratch (device globals; no allocation allowed)
__device__ __align__(16) float    g_xp[NPOS*CC];      // pooled input NHWC (fp32)
__device__ __align__(16) uint32_t g_xph[NPOS*CC/2];   // bf16 hi image, 2ch/u32
__device__ __align__(16) uint32_t g_xpl[NPOS*CC/2];   // bf16 lo residual image
__device__ __align__(16) float    g_tmp[NPOS*CC];     // horizontal pool sums (NCHW)
__device__ __align__(16) float    g_om[NPOS*32];      // per-pos offsets(18)+mask(9)
__device__ __align__(16) uint2 g_wf[NKB*8*32*32];     // deform W B-frags [kb][bsel][ntile][lane]
__device__ __align__(16) uint2 g_wfo[NKB*8*4*32];     // offmask W B-frags [kb][bsel][ntile(4)][lane]

// ============================ helpers ============================
__device__ __forceinline__ uint32_t smem_u32(const void* p) {
    uint32_t a;
    asm("{ .reg .u64 t; cvta.to.shared.u64 t, %1; cvt.u32.u64 %0, t; }" : "=r"(a) : "l"(p));
    return a;
}

__device__ __forceinline__ void ldsm4(uint32_t& a0, uint32_t& a1, uint32_t& a2,
                                      uint32_t& a3, uint32_t addr) {
    asm volatile("ldmatrix.sync.aligned.m8n8.x4.shared.b16 {%0,%1,%2,%3}, [%4];"
        : "=r"(a0), "=r"(a1), "=r"(a2), "=r"(a3) : "r"(addr));
}

__device__ __forceinline__ void mma16816(float* d, uint32_t a0, uint32_t a1,
                                         uint32_t a2, uint32_t a3,
                                         uint32_t b0, uint32_t b1) {
    asm volatile("mma.sync.aligned.m16n8k16.row.col.f32.bf16.bf16.f32 "
        "{%0,%1,%2,%3}, {%4,%5,%6,%7}, {%8,%9}, {%0,%1,%2,%3};"
        : "+f"(d[0]), "+f"(d[1]), "+f"(d[2]), "+f"(d[3])
        : "r"(a0), "r"(a1), "r"(a2), "r"(a3), "r"(b0), "r"(b1));
}

__device__ __forceinline__ uint32_t pack_bf16(float lo_k, float hi_k) {
    __nv_bfloat16 a = __float2bfloat16_rn(lo_k);
    __nv_bfloat16 b = __float2bfloat16_rn(hi_k);
    return ((uint32_t)__bfloat16_as_ushort(b) << 16) | __bfloat16_as_ushort(a);
}

// ---------------------------------------------------------------------------
// Kernel 1a: horizontal 3-sum (NCHW -> g_tmp NCHW)
// ---------------------------------------------------------------------------
__global__ void pool_h(const float* __restrict__ x) {
    int i = blockIdx.x * 256 + threadIdx.x;
    int w = i % WW;
    float s = x[i];
    if (w > 0)      s += x[i-1];
    if (w < WW-1)   s += x[i+1];
    g_tmp[i] = s;
}

// ---------------------------------------------------------------------------
// Kernel 1b: vertical 3-sum + /9 + transpose to NHWC (g_tmp -> g_xp)
// Also emits bf16 hi/lo images (g_xph/g_xpl), 2 channels packed per u32.
// ---------------------------------------------------------------------------
__global__ void pool_v() {
    __shared__ float tile[16][17];
    int id = blockIdx.x;
    int c0 = (id & 15) * 16; id >>= 4;
    int w0 = (id % 5) * 16;  id /= 5;
    int h  = id % HH;
    int b  = id / HH;
    int t  = threadIdx.x;
    int ci = t >> 4, wi = t & 15;
    int c = c0 + ci, wcol = w0 + wi;
    const float* xb = g_tmp + (b*CC + c) * HW;
    float s = 0.f;
#pragma unroll
    for (int dy = -1; dy <= 1; dy++) {
        int y = h + dy;
        if (y < 0 || y >= HH) continue;
        s += xb[y*WW + wcol];
    }
    tile[ci][wi] = s * (1.f/9.f);
    __syncthreads();
    int wi2 = t >> 4, ci2 = t & 15;
    int pos = (b*HH + h)*WW + w0 + wi2;
    float v0 = tile[ci2][wi2];
    g_xp[pos*CC + c0 + ci2] = v0;
    if ((ci2 & 1) == 0) {
        float v1 = tile[ci2+1][wi2];
        __nv_bfloat16 h0 = __float2bfloat16_rn(v0);
        __nv_bfloat16 h1 = __float2bfloat16_rn(v1);
        uint32_t hp = ((uint32_t)__bfloat16_as_ushort(h1) << 16)
                    | __bfloat16_as_ushort(h0);
        uint32_t lp = pack_bf16(v0 - __bfloat162float(h0),
                                v1 - __bfloat162float(h1));
        int idx = (pos*CC + c0 + ci2) >> 1;
        g_xph[idx] = hp;
        g_xpl[idx] = lp;
    }
}

// ---------------------------------------------------------------------------
// Kernel 2: weight prep — B fragments for mma.m16n8k16.row.col (hi/lo split)
// ---------------------------------------------------------------------------
#define NWF  (NKB*8*32*32)       // 294912 uint2 records
#define NWFO (NKB*8*4*32)        // 36864 uint2 records
__global__ void wprep_kernel(const float* __restrict__ off_w,
                             const float* __restrict__ mod_w,
                             const float* __restrict__ w) {
    int i = blockIdx.x * 256 + threadIdx.x;
    if (i < NWF) {
        int j = i;
        int lane = j & 31;
        int nt   = (j >> 5) & 31;
        int bsel = (j >> 10) & 7;
        int kb   = j >> 13;
        int kk = kb >> 2;
        int lo = bsel >> 2;
        int o  = nt*8 + (lane >> 2);
        int c0 = (kb & 3)*64 + (bsel & 3)*16 + 2*(lane & 3);
        float wv[4];
#pragma unroll
        for (int q = 0; q < 4; q++) {
            int c = c0 + (q >> 1)*8 + (q & 1);
            float f = w[(o*CC + c)*KK9 + kk];
            __nv_bfloat16 h = __float2bfloat16_rn(f);
            wv[q] = lo ? (f - __bfloat162float(h)) : f;
        }
        uint2 rec;
        rec.x = pack_bf16(wv[0], wv[1]);
        rec.y = pack_bf16(wv[2], wv[3]);
        g_wf[j] = rec;
    } else if (i < NWF + NWFO) {
        int j = i - NWF;
        int lane = j & 31;
        int nt   = (j >> 5) & 3;
        int bsel = (j >> 7) & 7;
        int kb   = j >> 10;
        int kk = kb >> 2;
        int lo = bsel >> 2;
        int o  = nt*8 + (lane >> 2);
        int c0 = (kb & 3)*64 + (bsel & 3)*16 + 2*(lane & 3);
        float wv[4];
#pragma unroll
        for (int q = 0; q < 4; q++) {
            int c = c0 + (q >> 1)*8 + (q & 1);
            float f = 0.f;
            if (o < 18)      f = off_w[(o*CC + c)*KK9 + kk];
            else if (o < 27) f = mod_w[((o-18)*CC + c)*KK9 + kk];
            __nv_bfloat16 h = __float2bfloat16_rn(f);
            wv[q] = lo ? (f - __bfloat162float(h)) : f;
        }
        uint2 rec;
        rec.x = pack_bf16(wv[0], wv[1]);
        rec.y = pack_bf16(wv[2], wv[3]);
        g_wfo[j] = rec;
    }
}

// ---------------------------------------------------------------------------
// Kernel 3: offset+mask conv via mma.sync bf16 (3-term hi/lo split).
// Block: 256 thr = 8 warps (2m x 4n). M=32 pos, N=32(27). Grid 800.
// (unchanged — measured 125-127 us)
// ---------------------------------------------------------------------------
__device__ __forceinline__ void om_gather(char* sA, const int* sBase, int kb,
                                          int buf, int t) {
    const uint4* xph4 = (const uint4*)g_xph;
    const uint4* xpl4 = (const uint4*)g_xpl;
    int kk = kb >> 2;
    int p = t >> 3, g = t & 7;          // 256 tasks: 32 pos x 8 groups of 8 ch
    int pos = sBase[kk*32 + p];
    uint4 hp = make_uint4(0u, 0u, 0u, 0u);
    uint4 lp = hp;
    if (pos >= 0) {
        int idx = pos*32 + (kb & 3)*8 + g;   // uint4 units: CC/8 = 32 per pos
        hp = xph4[idx];
        lp = xpl4[idx];
    }
    int off = p*128 + ((g*16) ^ ((p & 7) << 4));
    *(uint4*)(sA + buf*8192 + off)        = hp;
    *(uint4*)(sA + buf*8192 + 4096 + off) = lp;
}

__global__ void __launch_bounds__(256) offmask_kernel(const float* __restrict__ off_b,
                                                      const float* __restrict__ mod_b) {
    __shared__ __align__(16) char sA[2*8192];
    __shared__ int sBase[288];
    uint32_t sb = smem_u32(sA);

    int t = threadIdx.x, lane = t & 31, wid = t >> 5;
    int wm = wid >> 2, wn = wid & 3;       // 2m x 4n
    int pbase = blockIdx.x * 32;

    for (int q = t; q < 288; q += 256) {
        int tap = q >> 5, p = q & 31;
        int pgl = pbase + p;
        int b = pgl / HW, r = pgl % HW;
        int h = r / WW, w = r % WW;
        int y = h - 1 + tap/3, x = w - 1 + tap%3;
        sBase[q] = (((unsigned)y < HH) && ((unsigned)x < WW))
                   ? ((b*HH + y)*WW + x) : -1;
    }
    __syncthreads();

    om_gather(sA, sBase, 0, 0, t);
    __syncthreads();

    float acc[4] = {0.f, 0.f, 0.f, 0.f};

    int rowterm = (wm*16 + (lane & 15)) * 128;
    int kterm = ((lane >> 4) & 1) * 16;
    int swzl = (lane & 7) << 4;

    for (int kb = 0; kb < NKB; kb++) {
        int buf = kb & 1;
        if (kb + 1 < NKB) om_gather(sA, sBase, kb + 1, buf ^ 1, t);

        uint32_t Ah = sb + buf*8192;
        uint32_t Al = Ah + 4096;
        const uint2* gb = g_wfo + (size_t)kb*8*4*32 + wn*32 + lane;

        uint2 bfc = gb[0];
#pragma unroll 1
        for (int s = 0; s < 8; s++) {
            uint2 bfn = gb[(((s + 1) & 7) * 4) * 32];
            int off = ((s & 3)*32 + kterm) ^ swzl;
            uint32_t a0, a1, a2, a3;
            ldsm4(a0, a1, a2, a3, Ah + rowterm + off);
            mma16816(acc, a0, a1, a2, a3, bfc.x, bfc.y);
            if (s < 4) {
                ldsm4(a0, a1, a2, a3, Al + rowterm + off);
                mma16816(acc, a0, a1, a2, a3, bfc.x, bfc.y);
            }
            bfc = bfn;
        }
        __syncthreads();
    }

    // epilogue: bias / 2*sigmoid, direct stores to g_om
    int row = pbase + wm*16 + (lane >> 2);
    int col = wn*8 + 2*(lane & 3);
#pragma unroll
    for (int q = 0; q < 4; q++) {
        int cc = col + (q & 1);
        int rr = row + (q >> 1)*8;
        float v = acc[q];
        if (cc < 18)      v = v + off_b[cc];
        else if (cc < 27) v = 2.f / (1.f + expf(-(v + mod_b[cc-18])));
        else continue;
        g_om[rr*32 + cc] = v;
    }
}

// ---------------------------------------------------------------------------
// Kernel 4: deformable conv via mma.sync bf16 (3-term hi/lo split).
// Block: 256 thr = 8 warps (2m x 4n), M=32 pos, N=256. Grid 800.
// Static smem 43 KB -> 3 blocks/SM (launch_bounds(256,3), 85-reg cap).
// Mainloop identical to the verified 516-us configuration.
// ---------------------------------------------------------------------------
__device__ __align__(16) struct {} g_dummy;  // (no-op; keeps layout edits local)

struct DeformSmem {
    __align__(16) char  sU[32768];     // union: A bufs 2x(4096+4096)=16K / epi 32K
    __align__(16) float4 sCW[288];     // corner weights [tap][pos]
    __align__(16) int4   sCI[288];     // corner indices
    int   sOB[32];
    float sBias[256];
};

__device__ __forceinline__ void deform_gather(DeformSmem* sm, int kb, int buf,
                                              int t) {
    const float4* xp4 = (const float4*)g_xp;
    int kk = kb >> 2;
    int p = t >> 3, g = t & 7;          // 256 tasks: 32 pos x 8 groups of 8 ch
    float4 bw = sm->sCW[kk*32 + p];
    int4 iv = sm->sCI[kk*32 + p];
    float v[8];
    int fbase = (kb & 3)*16 + g*2;
#pragma unroll
    for (int j = 0; j < 2; j++) {
        int f = fbase + j;
        float4 a  = xp4[iv.x + f];
        float4 b2 = xp4[iv.y + f];
        float4 c2 = xp4[iv.z + f];
        float4 d2 = xp4[iv.w + f];
        v[4*j+0] = bw.x*a.x + bw.y*b2.x + bw.z*c2.x + bw.w*d2.x;
        v[4*j+1] = bw.x*a.y + bw.y*b2.y + bw.z*c2.y + bw.w*d2.y;
        v[4*j+2] = bw.x*a.z + bw.y*b2.z + bw.z*c2.z + bw.w*d2.z;
        v[4*j+3] = bw.x*a.w + bw.y*b2.w + bw.z*c2.w + bw.w*d2.w;
    }
    uint32_t hp[4], lp[4];
#pragma unroll
    for (int q = 0; q < 4; q++) {
        float a0 = v[2*q], a1 = v[2*q+1];
        __nv_bfloat16 h0 = __float2bfloat16_rn(a0);
        __nv_bfloat16 h1 = __float2bfloat16_rn(a1);
        hp[q] = ((uint32_t)__bfloat16_as_ushort(h1) << 16) | __bfloat16_as_ushort(h0);
        lp[q] = pack_bf16(a0 - __bfloat162float(h0), a1 - __bfloat162float(h1));
    }
    char* Ab = sm->sU + buf*8192;
    int off = p*128 + ((g*16) ^ ((p & 7) << 4));   // SW128 swizzle
    *(uint4*)(Ab + off)        = make_uint4(hp[0], hp[1], hp[2], hp[3]);
    *(uint4*)(Ab + 4096 + off) = make_uint4(lp[0], lp[1], lp[2], lp[3]);
}

__global__ void __launch_bounds__(256, 3) deform_kernel(const float* __restrict__ bias,
                                                        float* __restrict__ out) {
    __shared__ DeformSmem sm;
    uint32_t sb = smem_u32(sm.sU);

    int t = threadIdx.x, lane = t & 31, wid = t >> 5;
    int wm = wid >> 2, wn = wid & 3;    // 2m x 4n
    int pbase = blockIdx.x * 32;

    // corners for all 9 taps (288 = 9 x 32)
    for (int q = t; q < 288; q += 256) {
        int tap = q >> 5, p = q & 31;
        int pgl = pbase + p;
        int b = pgl / HW, r = pgl % HW;
        int h = r / WW, w = r % WW;
        float dy = g_om[pgl*32 + 2*tap];
        float dx = g_om[pgl*32 + 2*tap + 1];
        float m  = g_om[pgl*32 + 18 + tap];
        float py = (float)(h - 1 + tap/3) + dy;
        float px = (float)(w - 1 + tap%3) + dx;
        float fy = floorf(py), fx = floorf(px);
        int y0 = (int)fy, x0 = (int)fx;
        float wy = py - fy, wx = px - fx;
        int y1 = y0 + 1, x1 = x0 + 1;
        bool vy0 = (unsigned)y0 < HH, vy1 = (unsigned)y1 < HH;
        bool vx0 = (unsigned)x0 < WW, vx1 = (unsigned)x1 < WW;
        float4 wv;
        wv.x = (1.f-wy)*(1.f-wx)*m * (float)(vy0 && vx0);
        wv.y = (1.f-wy)*wx      *m * (float)(vy0 && vx1);
        wv.z = wy*(1.f-wx)      *m * (float)(vy1 && vx0);
        wv.w = wy*wx            *m * (float)(vy1 && vx1);
        int yc0 = min(max(y0, 0), HH-1), yc1 = min(max(y1, 0), HH-1);
        int xc0 = min(max(x0, 0), WW-1), xc1 = min(max(x1, 0), WW-1);
        int rowb = b*HH;
        int4 iv;
        iv.x = ((rowb + yc0)*WW + xc0) * (CC/4);
        iv.y = ((rowb + yc0)*WW + xc1) * (CC/4);
        iv.z = ((rowb + yc1)*WW + xc0) * (CC/4);
        iv.w = ((rowb + yc1)*WW + xc1) * (CC/4);
        sm.sCW[q] = wv;
        sm.sCI[q] = iv;
    }
    if (t < 32) {
        int pgl = pbase + t;
        sm.sOB[t] = (pgl / HW) * (CC*HW) + (pgl % HW);
    }
    sm.sBias[t] = bias[t];
    __syncthreads();

    deform_gather(&sm, 0, 0, t);
    __syncthreads();

    float acc[8][4];
#pragma unroll
    for (int nt = 0; nt < 8; nt++)
#pragma unroll
        for (int q = 0; q < 4; q++) acc[nt][q] = 0.f;

    int m0 = wm * 16;
    int rowterm = (m0 + (lane & 15)) * 128;
    int kterm = ((lane >> 4) & 1) * 16;
    int swzl = (lane & 7) << 4;

    for (int kb = 0; kb < NKB; kb++) {
        int buf = kb & 1;
        if (kb + 1 < NKB) deform_gather(&sm, kb + 1, buf ^ 1, t);

        uint32_t Ah = sb + buf*8192;
        uint32_t Al = Ah + 4096;
        const uint2* gbase = g_wf + ((size_t)kb*8*32 + wn*8) * 32 + lane;

        // hi-weight halves: A_hi and A_lo terms share B frags
#pragma unroll 1
        for (int h = 0; h < 4; h++) {
            uint2 bf[8];
#pragma unroll
            for (int nt = 0; nt < 8; nt++)
                bf[nt] = gbase[(h*32 + nt) * 32];
            int off = (h*32 + kterm) ^ swzl;
            uint32_t a0, a1, a2, a3;
            ldsm4(a0, a1, a2, a3, Ah + rowterm + off);
#pragma unroll
            for (int nt = 0; nt < 8; nt++)
                mma16816(acc[nt], a0, a1, a2, a3, bf[nt].x, bf[nt].y);
            ldsm4(a0, a1, a2, a3, Al + rowterm + off);
#pragma unroll
            for (int nt = 0; nt < 8; nt++)
                mma16816(acc[nt], a0, a1, a2, a3, bf[nt].x, bf[nt].y);
        }
        // lo-weight halves: A_hi only
#pragma unroll 1
        for (int h = 0; h < 4; h++) {
            uint2 bf[8];
#pragma unroll
            for (int nt = 0; nt < 8; nt++)
                bf[nt] = gbase[((4 + h)*32 + nt) * 32];
            int off = (h*32 + kterm) ^ swzl;
            uint32_t a0, a1, a2, a3;
            ldsm4(a0, a1, a2, a3, Ah + rowterm + off);
#pragma unroll
            for (int nt = 0; nt < 8; nt++)
                mma16816(acc[nt], a0, a1, a2, a3, bf[nt].x, bf[nt].y);
        }
        __syncthreads();
    }

    // epilogue: acc -> smem (reuse A region) -> coalesced NCHW stores
    float* sEp = (float*)sm.sU;   // [o][m] = [256][32]
    int rr = lane >> 2, cc = 2*(lane & 3);
#pragma unroll
    for (int nt = 0; nt < 8; nt++) {
        int n = (wn*8 + nt)*8 + cc;
        int m = m0 + rr;
        sEp[n*32 + m]         = acc[nt][0];
        sEp[(n+1)*32 + m]     = acc[nt][1];
        sEp[n*32 + m + 8]     = acc[nt][2];
        sEp[(n+1)*32 + m + 8] = acc[nt][3];
    }
    __syncthreads();
#pragma unroll
    for (int i = 0; i < 32; i++) {
        int idx = i*256 + t;
        int m = idx & 31, o = idx >> 5;
        out[sm.sOB[m] + o*HW] = sEp[idx] + sm.sBias[o];
    }
}

// ---------------------------------------------------------------------------
extern "C" void kernel_launch(void* const* d_in, const int* in_sizes, int n_in,
                              void* d_out, int out_size) {
    const float* x     = (const float*)d_in[0];
    const float* off_w = (const float*)d_in[1];
    const float* off_b = (const float*)d_in[2];
    const float* mod_w = (const float*)d_in[3];
    const float* mod_b = (const float*)d_in[4];
    const float* w     = (const float*)d_in[5];
    const float* b     = (const float*)d_in[6];
    float* out = (float*)d_out;

    pool_h<<<(NPOS*CC)/256, 256>>>(x);
    pool_v<<<BB*HH*5*16, 256>>>();
    wprep_kernel<<<(NWF + NWFO + 255)/256, 256>>>(off_w, mod_w, w);
    offmask_kernel<<<NPOS/32, 256>>>(off_b, mod_b);
    deform_kernel<<<NPOS/32, 256>>>(b, out);
}

// round 12
// speedup vs baseline: 2.2460x; 1.8046x over previous
#include <cuda_runtime.h>
#include <cuda_bf16.h>
#include <cuda_fp16.h>
#include <stdint.h>
#include <math.h>

// Problem constants
#define BB 4
#define CC 256
#define HH 80
#define WW 80
#define KK9 9
#define HW (HH*WW)
#define NPOS (BB*HW)             // 25600
#define NKB 36                   // K chunks: 9 taps x 4 chunks of 64 channels

// Scratch (device globals; no allocation allowed)
__device__ __align__(16) float    g_xp[NPOS*CC];      // pooled input NHWC (fp32)
__device__ __align__(16) uint32_t g_xph[NPOS*CC/2];   // fp16 image, 2ch/u32
__device__ __align__(16) float    g_tmp[NPOS*CC];     // horizontal pool sums (NCHW)
__device__ __align__(16) float    g_om[NPOS*32];      // per-pos offsets(18)+mask(9)
__device__ __align__(16) uint2 g_wf[NKB*4*32*32];     // deform W frags [kb][khalf][ntile][lane]
__device__ __align__(16) uint2 g_wfo[NKB*4*4*32];     // offmask W frags [kb][khalf][ntile(4)][lane]

// ============================ helpers ============================
__device__ __forceinline__ uint32_t smem_u32(const void* p) {
    uint32_t a;
    asm("{ .reg .u64 t; cvta.to.shared.u64 t, %1; cvt.u32.u64 %0, t; }" : "=r"(a) : "l"(p));
    return a;
}

__device__ __forceinline__ void ldsm4(uint32_t& a0, uint32_t& a1, uint32_t& a2,
                                      uint32_t& a3, uint32_t addr) {
    asm volatile("ldmatrix.sync.aligned.m8n8.x4.shared.b16 {%0,%1,%2,%3}, [%4];"
        : "=r"(a0), "=r"(a1), "=r"(a2), "=r"(a3) : "r"(addr));
}

__device__ __forceinline__ void mma16816(float* d, uint32_t a0, uint32_t a1,
                                         uint32_t a2, uint32_t a3,
                                         uint32_t b0, uint32_t b1) {
    asm volatile("mma.sync.aligned.m16n8k16.row.col.f32.f16.f16.f32 "
        "{%0,%1,%2,%3}, {%4,%5,%6,%7}, {%8,%9}, {%0,%1,%2,%3};"
        : "+f"(d[0]), "+f"(d[1]), "+f"(d[2]), "+f"(d[3])
        : "r"(a0), "r"(a1), "r"(a2), "r"(a3), "r"(b0), "r"(b1));
}

// pack two floats as fp16x2: low half = a, high half = b
__device__ __forceinline__ uint32_t pack_f16(float a, float b) {
    uint32_t r;
    asm("cvt.rn.f16x2.f32 %0, %1, %2;" : "=r"(r) : "f"(b), "f"(a));
    return r;
}

// ---------------------------------------------------------------------------
// Kernel 1a: horizontal 3-sum (NCHW -> g_tmp NCHW)
// ---------------------------------------------------------------------------
__global__ void pool_h(const float* __restrict__ x) {
    int i = blockIdx.x * 256 + threadIdx.x;
    int w = i % WW;
    float s = x[i];
    if (w > 0)      s += x[i-1];
    if (w < WW-1)   s += x[i+1];
    g_tmp[i] = s;
}

// ---------------------------------------------------------------------------
// Kernel 1b: vertical 3-sum + /9 + transpose to NHWC (g_tmp -> g_xp)
// Also emits the fp16 image g_xph (2 channels packed per u32).
// ---------------------------------------------------------------------------
__global__ void pool_v() {
    __shared__ float tile[16][17];
    int id = blockIdx.x;
    int c0 = (id & 15) * 16; id >>= 4;
    int w0 = (id % 5) * 16;  id /= 5;
    int h  = id % HH;
    int b  = id / HH;
    int t  = threadIdx.x;
    int ci = t >> 4, wi = t & 15;
    int c = c0 + ci, wcol = w0 + wi;
    const float* xb = g_tmp + (b*CC + c) * HW;
    float s = 0.f;
#pragma unroll
    for (int dy = -1; dy <= 1; dy++) {
        int y = h + dy;
        if (y < 0 || y >= HH) continue;
        s += xb[y*WW + wcol];
    }
    tile[ci][wi] = s * (1.f/9.f);
    __syncthreads();
    int wi2 = t >> 4, ci2 = t & 15;
    int pos = (b*HH + h)*WW + w0 + wi2;
    float v0 = tile[ci2][wi2];
    g_xp[pos*CC + c0 + ci2] = v0;
    if ((ci2 & 1) == 0) {
        float v1 = tile[ci2+1][wi2];
        g_xph[(pos*CC + c0 + ci2) >> 1] = pack_f16(v0, v1);
    }
}

// ---------------------------------------------------------------------------
// Kernel 2: weight prep — fp16 B fragments for mma.m16n8k16.row.col
//   g_wf  (deform):  [kb][khalf(4)][ntile(32)][lane]
//   g_wfo (offmask): [kb][khalf(4)][ntile(4)][lane], o<27 real else 0
// ---------------------------------------------------------------------------
#define NWF  (NKB*4*32*32)       // 147456 uint2 records
#define NWFO (NKB*4*4*32)        // 18432 uint2 records
__global__ void wprep_kernel(const float* __restrict__ off_w,
                             const float* __restrict__ mod_w,
                             const float* __restrict__ w) {
    int i = blockIdx.x * 256 + threadIdx.x;
    if (i < NWF) {
        int j = i;
        int lane  = j & 31;
        int nt    = (j >> 5) & 31;
        int khalf = (j >> 10) & 3;
        int kb    = j >> 12;
        int kk = kb >> 2;
        int o  = nt*8 + (lane >> 2);
        int c0 = (kb & 3)*64 + khalf*16 + 2*(lane & 3);
        float wv[4];
#pragma unroll
        for (int q = 0; q < 4; q++) {
            int c = c0 + (q >> 1)*8 + (q & 1);
            wv[q] = w[(o*CC + c)*KK9 + kk];
        }
        uint2 rec;
        rec.x = pack_f16(wv[0], wv[1]);
        rec.y = pack_f16(wv[2], wv[3]);
        g_wf[j] = rec;
    } else if (i < NWF + NWFO) {
        int j = i - NWF;
        int lane  = j & 31;
        int nt    = (j >> 5) & 3;
        int khalf = (j >> 7) & 3;
        int kb    = j >> 9;
        int kk = kb >> 2;
        int o  = nt*8 + (lane >> 2);
        int c0 = (kb & 3)*64 + khalf*16 + 2*(lane & 3);
        float wv[4];
#pragma unroll
        for (int q = 0; q < 4; q++) {
            int c = c0 + (q >> 1)*8 + (q & 1);
            float f = 0.f;
            if (o < 18)      f = off_w[(o*CC + c)*KK9 + kk];
            else if (o < 27) f = mod_w[((o-18)*CC + c)*KK9 + kk];
            wv[q] = f;
        }
        uint2 rec;
        rec.x = pack_f16(wv[0], wv[1]);
        rec.y = pack_f16(wv[2], wv[3]);
        g_wfo[j] = rec;
    }
}

// ---------------------------------------------------------------------------
// Kernel 3: offset+mask conv via mma.sync fp16 (single term).
// Block: 256 thr = 8 warps (2m x 4n). M=32 pos, N=32(27). Grid 800.
// ---------------------------------------------------------------------------
__device__ __forceinline__ void om_gather(char* sA, const int* sBase, int kb,
                                          int buf, int t) {
    const uint4* xph4 = (const uint4*)g_xph;
    int kk = kb >> 2;
    int p = t >> 3, g = t & 7;          // 256 tasks: 32 pos x 8 groups of 8 ch
    int pos = sBase[kk*32 + p];
    uint4 hp = make_uint4(0u, 0u, 0u, 0u);
    if (pos >= 0) hp = xph4[pos*32 + (kb & 3)*8 + g];
    int off = p*128 + ((g*16) ^ ((p & 7) << 4));
    *(uint4*)(sA + buf*4096 + off) = hp;
}

__global__ void __launch_bounds__(256) offmask_kernel(const float* __restrict__ off_b,
                                                      const float* __restrict__ mod_b) {
    __shared__ __align__(16) char sA[2*4096];
    __shared__ int sBase[288];
    uint32_t sb = smem_u32(sA);

    int t = threadIdx.x, lane = t & 31, wid = t >> 5;
    int wm = wid >> 2, wn = wid & 3;       // 2m x 4n
    int pbase = blockIdx.x * 32;

    for (int q = t; q < 288; q += 256) {
        int tap = q >> 5, p = q & 31;
        int pgl = pbase + p;
        int b = pgl / HW, r = pgl % HW;
        int h = r / WW, w = r % WW;
        int y = h - 1 + tap/3, x = w - 1 + tap%3;
        sBase[q] = (((unsigned)y < HH) && ((unsigned)x < WW))
                   ? ((b*HH + y)*WW + x) : -1;
    }
    __syncthreads();

    om_gather(sA, sBase, 0, 0, t);
    __syncthreads();

    float acc[4] = {0.f, 0.f, 0.f, 0.f};

    int rowterm = (wm*16 + (lane & 15)) * 128;
    int kterm = ((lane >> 4) & 1) * 16;
    int swzl = (lane & 7) << 4;

    for (int kb = 0; kb < NKB; kb++) {
        int buf = kb & 1;
        if (kb + 1 < NKB) om_gather(sA, sBase, kb + 1, buf ^ 1, t);

        uint32_t Ah = sb + buf*4096;
        const uint2* gb = g_wfo + (size_t)kb*4*4*32 + wn*32 + lane;

        uint2 bfc = gb[0];
#pragma unroll 1
        for (int s = 0; s < 4; s++) {
            uint2 bfn = gb[(((s + 1) & 3) * 4) * 32];
            int off = (s*32 + kterm) ^ swzl;
            uint32_t a0, a1, a2, a3;
            ldsm4(a0, a1, a2, a3, Ah + rowterm + off);
            mma16816(acc, a0, a1, a2, a3, bfc.x, bfc.y);
            bfc = bfn;
        }
        __syncthreads();
    }

    // epilogue: bias / 2*sigmoid, direct stores to g_om
    int row = pbase + wm*16 + (lane >> 2);
    int col = wn*8 + 2*(lane & 3);
#pragma unroll
    for (int q = 0; q < 4; q++) {
        int cc = col + (q & 1);
        int rr = row + (q >> 1)*8;
        float v = acc[q];
        if (cc < 18)      v = v + off_b[cc];
        else if (cc < 27) v = 2.f / (1.f + expf(-(v + mod_b[cc-18])));
        else continue;
        g_om[rr*32 + cc] = v;
    }
}

// ---------------------------------------------------------------------------
// Kernel 4: deformable conv via mma.sync fp16 (single term).
// Block: 256 thr = 8 warps (2m x 4n), M=32 pos, N=256. Grid 800.
// ---------------------------------------------------------------------------
struct DeformSmem {
    __align__(16) char  sU[32768];     // union: A bufs 2x4096 = 8K / epi 32K
    __align__(16) float4 sCW[288];     // corner weights [tap][pos]
    __align__(16) int4   sCI[288];     // corner indices
    int   sOB[32];
    float sBias[256];
};

__device__ __forceinline__ void deform_gather(DeformSmem* sm, int kb, int buf,
                                              int t) {
    const float4* xp4 = (const float4*)g_xp;
    int kk = kb >> 2;
    int p = t >> 3, g = t & 7;          // 256 tasks: 32 pos x 8 groups of 8 ch
    float4 bw = sm->sCW[kk*32 + p];
    int4 iv = sm->sCI[kk*32 + p];
    float v[8];
    int fbase = (kb & 3)*16 + g*2;
#pragma unroll
    for (int j = 0; j < 2; j++) {
        int f = fbase + j;
        float4 a  = xp4[iv.x + f];
        float4 b2 = xp4[iv.y + f];
        float4 c2 = xp4[iv.z + f];
        float4 d2 = xp4[iv.w + f];
        v[4*j+0] = bw.x*a.x + bw.y*b2.x + bw.z*c2.x + bw.w*d2.x;
        v[4*j+1] = bw.x*a.y + bw.y*b2.y + bw.z*c2.y + bw.w*d2.y;
        v[4*j+2] = bw.x*a.z + bw.y*b2.z + bw.z*c2.z + bw.w*d2.z;
        v[4*j+3] = bw.x*a.w + bw.y*b2.w + bw.z*c2.w + bw.w*d2.w;
    }
    uint32_t hp[4];
#pragma unroll
    for (int q = 0; q < 4; q++)
        hp[q] = pack_f16(v[2*q], v[2*q+1]);
    char* Ab = sm->sU + buf*4096;
    int off = p*128 + ((g*16) ^ ((p & 7) << 4));   // SW128 swizzle
    *(uint4*)(Ab + off) = make_uint4(hp[0], hp[1], hp[2], hp[3]);
}

__global__ void __launch_bounds__(256, 3) deform_kernel(const float* __restrict__ bias,
                                                        float* __restrict__ out) {
    __shared__ DeformSmem sm;
    uint32_t sb = smem_u32(sm.sU);

    int t = threadIdx.x, lane = t & 31, wid = t >> 5;
    int wm = wid >> 2, wn = wid & 3;    // 2m x 4n
    int pbase = blockIdx.x * 32;

    // corners for all 9 taps (288 = 9 x 32)
    for (int q = t; q < 288; q += 256) {
        int tap = q >> 5, p = q & 31;
        int pgl = pbase + p;
        int b = pgl / HW, r = pgl % HW;
        int h = r / WW, w = r % WW;
        float dy = g_om[pgl*32 + 2*tap];
        float dx = g_om[pgl*32 + 2*tap + 1];
        float m  = g_om[pgl*32 + 18 + tap];
        float py = (float)(h - 1 + tap/3) + dy;
        float px = (float)(w - 1 + tap%3) + dx;
        float fy = floorf(py), fx = floorf(px);
        int y0 = (int)fy, x0 = (int)fx;
        float wy = py - fy, wx = px - fx;
        int y1 = y0 + 1, x1 = x0 + 1;
        bool vy0 = (unsigned)y0 < HH, vy1 = (unsigned)y1 < HH;
        bool vx0 = (unsigned)x0 < WW, vx1 = (unsigned)x1 < WW;
        float4 wv;
        wv.x = (1.f-wy)*(1.f-wx)*m * (float)(vy0 && vx0);
        wv.y = (1.f-wy)*wx      *m * (float)(vy0 && vx1);
        wv.z = wy*(1.f-wx)      *m * (float)(vy1 && vx0);
        wv.w = wy*wx            *m * (float)(vy1 && vx1);
        int yc0 = min(max(y0, 0), HH-1), yc1 = min(max(y1, 0), HH-1);
        int xc0 = min(max(x0, 0), WW-1), xc1 = min(max(x1, 0), WW-1);
        int rowb = b*HH;
        int4 iv;
        iv.x = ((rowb + yc0)*WW + xc0) * (CC/4);
        iv.y = ((rowb + yc0)*WW + xc1) * (CC/4);
        iv.z = ((rowb + yc1)*WW + xc0) * (CC/4);
        iv.w = ((rowb + yc1)*WW + xc1) * (CC/4);
        sm.sCW[q] = wv;
        sm.sCI[q] = iv;
    }
    if (t < 32) {
        int pgl = pbase + t;
        sm.sOB[t] = (pgl / HW) * (CC*HW) + (pgl % HW);
    }
    sm.sBias[t] = bias[t];
    __syncthreads();

    deform_gather(&sm, 0, 0, t);
    __syncthreads();

    float acc[8][4];
#pragma unroll
    for (int nt = 0; nt < 8; nt++)
#pragma unroll
        for (int q = 0; q < 4; q++) acc[nt][q] = 0.f;

    int m0 = wm * 16;
    int rowterm = (m0 + (lane & 15)) * 128;
    int kterm = ((lane >> 4) & 1) * 16;
    int swzl = (lane & 7) << 4;

    for (int kb = 0; kb < NKB; kb++) {
        int buf = kb & 1;
        if (kb + 1 < NKB) deform_gather(&sm, kb + 1, buf ^ 1, t);

        uint32_t Ah = sb + buf*4096;
        const uint2* gbase = g_wf + ((size_t)kb*4*32 + wn*8) * 32 + lane;

#pragma unroll 1
        for (int h = 0; h < 4; h++) {
            uint2 bf[8];
#pragma unroll
            for (int nt = 0; nt < 8; nt++)
                bf[nt] = gbase[(h*32 + nt) * 32];
            int off = (h*32 + kterm) ^ swzl;
            uint32_t a0, a1, a2, a3;
            ldsm4(a0, a1, a2, a3, Ah + rowterm + off);
#pragma unroll
            for (int nt = 0; nt < 8; nt++)
                mma16816(acc[nt], a0, a1, a2, a3, bf[nt].x, bf[nt].y);
        }
        __syncthreads();
    }

    // epilogue: acc -> smem (reuse A region) -> coalesced NCHW stores
    float* sEp = (float*)sm.sU;   // [o][m] = [256][32]
    int rr = lane >> 2, cc = 2*(lane & 3);
#pragma unroll
    for (int nt = 0; nt < 8; nt++) {
        int n = (wn*8 + nt)*8 + cc;
        int m = m0 + rr;
        sEp[n*32 + m]         = acc[nt][0];
        sEp[(n+1)*32 + m]     = acc[nt][1];
        sEp[n*32 + m + 8]     = acc[nt][2];
        sEp[(n+1)*32 + m + 8] = acc[nt][3];
    }
    __syncthreads();
#pragma unroll
    for (int i = 0; i < 32; i++) {
        int idx = i*256 + t;
        int m = idx & 31, o = idx >> 5;
        out[sm.sOB[m] + o*HW] = sEp[idx] + sm.sBias[o];
    }
}

// ---------------------------------------------------------------------------
extern "C" void kernel_launch(void* const* d_in, const int* in_sizes, int n_in,
                              void* d_out, int out_size) {
    const float* x     = (const float*)d_in[0];
    const float* off_w = (const float*)d_in[1];
    const float* off_b = (const float*)d_in[2];
    const float* mod_w = (const float*)d_in[3];
    const float* mod_b = (const float*)d_in[4];
    const float* w     = (const float*)d_in[5];
    const float* b     = (const float*)d_in[6];
    float* out = (float*)d_out;

    pool_h<<<(NPOS*CC)/256, 256>>>(x);
    pool_v<<<BB*HH*5*16, 256>>>();
    wprep_kernel<<<(NWF + NWFO + 255)/256, 256>>>(off_w, mod_w, w);
    offmask_kernel<<<NPOS/32, 256>>>(off_b, mod_b);
    deform_kernel<<<NPOS/32, 256>>>(b, out);
}

// round 14
// speedup vs baseline: 2.3889x; 1.0636x over previous
#include <cuda_runtime.h>
#include <cuda_bf16.h>
#include <cuda_fp16.h>
#include <stdint.h>
#include <math.h>

// Problem constants
#define BB 4
#define CC 256
#define HH 80
#define WW 80
#define KK9 9
#define HW (HH*WW)
#define NPOS (BB*HW)             // 25600
#define NKB 36                   // K chunks: 9 taps x 4 chunks of 64 channels

// Scratch (device globals; no allocation allowed)
__device__ __align__(16) float    g_xp[NPOS*CC];      // pooled input NHWC (fp32)
__device__ __align__(16) uint32_t g_xph[NPOS*CC/2];   // fp16 image, 2ch/u32
__device__ __align__(16) float    g_tmp[NPOS*CC];     // horizontal pool sums (NCHW)
__device__ __align__(16) float    g_om[NPOS*32];      // per-pos offsets(18)+mask(9)
__device__ __align__(16) uint2 g_wf[NKB*4*32*32];     // deform W frags [kb][khalf][ntile][lane]
__device__ __align__(16) uint2 g_wfo[NKB*4*4*32];     // offmask W frags [kb][khalf][ntile(4)][lane]

// ============================ helpers ============================
__device__ __forceinline__ uint32_t smem_u32(const void* p) {
    uint32_t a;
    asm("{ .reg .u64 t; cvta.to.shared.u64 t, %1; cvt.u32.u64 %0, t; }" : "=r"(a) : "l"(p));
    return a;
}

__device__ __forceinline__ void ldsm4(uint32_t& a0, uint32_t& a1, uint32_t& a2,
                                      uint32_t& a3, uint32_t addr) {
    asm volatile("ldmatrix.sync.aligned.m8n8.x4.shared.b16 {%0,%1,%2,%3}, [%4];"
        : "=r"(a0), "=r"(a1), "=r"(a2), "=r"(a3) : "r"(addr));
}

__device__ __forceinline__ void mma16816(float* d, uint32_t a0, uint32_t a1,
                                         uint32_t a2, uint32_t a3,
                                         uint32_t b0, uint32_t b1) {
    asm volatile("mma.sync.aligned.m16n8k16.row.col.f32.f16.f16.f32 "
        "{%0,%1,%2,%3}, {%4,%5,%6,%7}, {%8,%9}, {%0,%1,%2,%3};"
        : "+f"(d[0]), "+f"(d[1]), "+f"(d[2]), "+f"(d[3])
        : "r"(a0), "r"(a1), "r"(a2), "r"(a3), "r"(b0), "r"(b1));
}

// pack two floats as fp16x2: low half = a, high half = b
__device__ __forceinline__ uint32_t pack_f16(float a, float b) {
    uint32_t r;
    asm("cvt.rn.f16x2.f32 %0, %1, %2;" : "=r"(r) : "f"(b), "f"(a));
    return r;
}

// ---------------------------------------------------------------------------
// Kernel 1a: horizontal 3-sum (NCHW -> g_tmp NCHW)
// ---------------------------------------------------------------------------
__global__ void pool_h(const float* __restrict__ x) {
    int i = blockIdx.x * 256 + threadIdx.x;
    int w = i % WW;
    float s = x[i];
    if (w > 0)      s += x[i-1];
    if (w < WW-1)   s += x[i+1];
    g_tmp[i] = s;
}

// ---------------------------------------------------------------------------
// Kernel 1b: vertical 3-sum + /9 + transpose to NHWC (g_tmp -> g_xp)
// Also emits the fp16 image g_xph (2 channels packed per u32).
// ---------------------------------------------------------------------------
__global__ void pool_v() {
    __shared__ float tile[16][17];
    int id = blockIdx.x;
    int c0 = (id & 15) * 16; id >>= 4;
    int w0 = (id % 5) * 16;  id /= 5;
    int h  = id % HH;
    int b  = id / HH;
    int t  = threadIdx.x;
    int ci = t >> 4, wi = t & 15;
    int c = c0 + ci, wcol = w0 + wi;
    const float* xb = g_tmp + (b*CC + c) * HW;
    float s = 0.f;
#pragma unroll
    for (int dy = -1; dy <= 1; dy++) {
        int y = h + dy;
        if (y < 0 || y >= HH) continue;
        s += xb[y*WW + wcol];
    }
    tile[ci][wi] = s * (1.f/9.f);
    __syncthreads();
    int wi2 = t >> 4, ci2 = t & 15;
    int pos = (b*HH + h)*WW + w0 + wi2;
    float v0 = tile[ci2][wi2];
    g_xp[pos*CC + c0 + ci2] = v0;
    if ((ci2 & 1) == 0) {
        float v1 = tile[ci2+1][wi2];
        g_xph[(pos*CC + c0 + ci2) >> 1] = pack_f16(v0, v1);
    }
}

// ---------------------------------------------------------------------------
// Kernel 2: weight prep — fp16 B fragments for mma.m16n8k16.row.col
// ---------------------------------------------------------------------------
#define NWF  (NKB*4*32*32)       // 147456 uint2 records
#define NWFO (NKB*4*4*32)        // 18432 uint2 records
__global__ void wprep_kernel(const float* __restrict__ off_w,
                             const float* __restrict__ mod_w,
                             const float* __restrict__ w) {
    int i = blockIdx.x * 256 + threadIdx.x;
    if (i < NWF) {
        int j = i;
        int lane  = j & 31;
        int nt    = (j >> 5) & 31;
        int khalf = (j >> 10) & 3;
        int kb    = j >> 12;
        int kk = kb >> 2;
        int o  = nt*8 + (lane >> 2);
        int c0 = (kb & 3)*64 + khalf*16 + 2*(lane & 3);
        float wv[4];
#pragma unroll
        for (int q = 0; q < 4; q++) {
            int c = c0 + (q >> 1)*8 + (q & 1);
            wv[q] = w[(o*CC + c)*KK9 + kk];
        }
        uint2 rec;
        rec.x = pack_f16(wv[0], wv[1]);
        rec.y = pack_f16(wv[2], wv[3]);
        g_wf[j] = rec;
    } else if (i < NWF + NWFO) {
        int j = i - NWF;
        int lane  = j & 31;
        int nt    = (j >> 5) & 3;
        int khalf = (j >> 7) & 3;
        int kb    = j >> 9;
        int kk = kb >> 2;
        int o  = nt*8 + (lane >> 2);
        int c0 = (kb & 3)*64 + khalf*16 + 2*(lane & 3);
        float wv[4];
#pragma unroll
        for (int q = 0; q < 4; q++) {
            int c = c0 + (q >> 1)*8 + (q & 1);
            float f = 0.f;
            if (o < 18)      f = off_w[(o*CC + c)*KK9 + kk];
            else if (o < 27) f = mod_w[((o-18)*CC + c)*KK9 + kk];
            wv[q] = f;
        }
        uint2 rec;
        rec.x = pack_f16(wv[0], wv[1]);
        rec.y = pack_f16(wv[2], wv[3]);
        g_wfo[j] = rec;
    }
}

// ---------------------------------------------------------------------------
// Kernel 3: offset+mask conv via mma.sync fp16, full-tap phases (K=256).
// Block: 256 thr = 8 warps (2m x 4n). M=32 pos, N=32(27). Grid 800. 9 syncs.
// ---------------------------------------------------------------------------
__device__ __forceinline__ void om_gather(char* sA, const int* sBase, int tap,
                                          int buf, int t) {
    const uint4* xph4 = (const uint4*)g_xph;
    int p = t >> 3, g = t & 7;
    int pos = sBase[tap*32 + p];
    char* Ab = sA + buf*16384;
    int off = p*128 + ((g*16) ^ ((p & 7) << 4));
#pragma unroll
    for (int c4 = 0; c4 < 4; c4++) {
        uint4 hp = make_uint4(0u, 0u, 0u, 0u);
        if (pos >= 0) hp = xph4[pos*32 + c4*8 + g];
        *(uint4*)(Ab + c4*4096 + off) = hp;
    }
}

__global__ void __launch_bounds__(256) offmask_kernel(const float* __restrict__ off_b,
                                                      const float* __restrict__ mod_b) {
    __shared__ __align__(16) char sA[2*16384];
    __shared__ int sBase[288];
    uint32_t sb = smem_u32(sA);

    int t = threadIdx.x, lane = t & 31, wid = t >> 5;
    int wm = wid >> 2, wn = wid & 3;       // 2m x 4n
    int pbase = blockIdx.x * 32;

    for (int q = t; q < 288; q += 256) {
        int tap = q >> 5, p = q & 31;
        int pgl = pbase + p;
        int b = pgl / HW, r = pgl % HW;
        int h = r / WW, w = r % WW;
        int y = h - 1 + tap/3, x = w - 1 + tap%3;
        sBase[q] = (((unsigned)y < HH) && ((unsigned)x < WW))
                   ? ((b*HH + y)*WW + x) : -1;
    }
    __syncthreads();

    om_gather(sA, sBase, 0, 0, t);
    __syncthreads();

    float acc[4] = {0.f, 0.f, 0.f, 0.f};

    int rowterm = (wm*16 + (lane & 15)) * 128;
    int kterm = ((lane >> 4) & 1) * 16;
    int swzl = (lane & 7) << 4;

    for (int tap = 0; tap < 9; tap++) {
        int buf = tap & 1;
        if (tap + 1 < 9) om_gather(sA, sBase, tap + 1, buf ^ 1, t);

#pragma unroll 1
        for (int c4 = 0; c4 < 4; c4++) {
            uint32_t Ah = sb + buf*16384 + c4*4096;
            const uint2* gb = g_wfo + (size_t)(tap*4 + c4)*4*4*32 + wn*32 + lane;
#pragma unroll
            for (int s = 0; s < 4; s++) {
                uint2 bf = gb[(s*4) * 32];
                int off = (s*32 + kterm) ^ swzl;
                uint32_t a0, a1, a2, a3;
                ldsm4(a0, a1, a2, a3, Ah + rowterm + off);
                mma16816(acc, a0, a1, a2, a3, bf.x, bf.y);
            }
        }
        __syncthreads();
    }

    // epilogue: bias / 2*sigmoid, direct stores to g_om
    int row = pbase + wm*16 + (lane >> 2);
    int col = wn*8 + 2*(lane & 3);
#pragma unroll
    for (int q = 0; q < 4; q++) {
        int cc = col + (q & 1);
        int rr = row + (q >> 1)*8;
        float v = acc[q];
        if (cc < 18)      v = v + off_b[cc];
        else if (cc < 27) v = 2.f / (1.f + expf(-(v + mod_b[cc-18])));
        else continue;
        g_om[rr*32 + cc] = v;
    }
}

// ---------------------------------------------------------------------------
// Kernel 4: deformable conv via mma.sync fp16, full-tap phases (K=256).
// Block: 256 thr = 8 warps (2m x 4n), M=32 pos, N=256. Grid 800. 9 syncs.
// ---------------------------------------------------------------------------
struct DeformSmem {
    __align__(16) char  sU[32768];     // union: A bufs 2x16384 / epi 32K
    __align__(16) float4 sCW[288];     // corner weights [tap][pos]
    __align__(16) int4   sCI[288];     // corner indices
    int   sOB[32];
    float sBias[256];
};

__device__ __forceinline__ void deform_gather(DeformSmem* sm, int tap, int buf,
                                              int t) {
    const float4* xp4 = (const float4*)g_xp;
    int p = t >> 3, g = t & 7;
    float4 bw = sm->sCW[tap*32 + p];
    int4 iv = sm->sCI[tap*32 + p];
    char* Ab = sm->sU + buf*16384;
    int off = p*128 + ((g*16) ^ ((p & 7) << 4));
#pragma unroll
    for (int c4 = 0; c4 < 4; c4++) {
        float v[8];
        int fbase = c4*16 + g*2;
#pragma unroll
        for (int j = 0; j < 2; j++) {
            int f = fbase + j;
            float4 a  = xp4[iv.x + f];
            float4 b2 = xp4[iv.y + f];
            float4 c2 = xp4[iv.z + f];
            float4 d2 = xp4[iv.w + f];
            v[4*j+0] = bw.x*a.x + bw.y*b2.x + bw.z*c2.x + bw.w*d2.x;
            v[4*j+1] = bw.x*a.y + bw.y*b2.y + bw.z*c2.y + bw.w*d2.y;
            v[4*j+2] = bw.x*a.z + bw.y*b2.z + bw.z*c2.z + bw.w*d2.z;
            v[4*j+3] = bw.x*a.w + bw.y*b2.w + bw.z*c2.w + bw.w*d2.w;
        }
        uint4 hp;
        hp.x = pack_f16(v[0], v[1]);
        hp.y = pack_f16(v[2], v[3]);
        hp.z = pack_f16(v[4], v[5]);
        hp.w = pack_f16(v[6], v[7]);
        *(uint4*)(Ab + c4*4096 + off) = hp;
    }
}

__global__ void __launch_bounds__(256, 3) deform_kernel(const float* __restrict__ bias,
                                                        float* __restrict__ out) {
    __shared__ DeformSmem sm;
    uint32_t sb = smem_u32(sm.sU);

    int t = threadIdx.x, lane = t & 31, wid = t >> 5;
    int wm = wid >> 2, wn = wid & 3;    // 2m x 4n
    int pbase = blockIdx.x * 32;

    // corners for all 9 taps (288 = 9 x 32)
    for (int q = t; q < 288; q += 256) {
        int tap = q >> 5, p = q & 31;
        int pgl = pbase + p;
        int b = pgl / HW, r = pgl % HW;
        int h = r / WW, w = r % WW;
        float dy = g_om[pgl*32 + 2*tap];
        float dx = g_om[pgl*32 + 2*tap + 1];
        float m  = g_om[pgl*32 + 18 + tap];
        float py = (float)(h - 1 + tap/3) + dy;
        float px = (float)(w - 1 + tap%3) + dx;
        float fy = floorf(py), fx = floorf(px);
        int y0 = (int)fy, x0 = (int)fx;
        float wy = py - fy, wx = px - fx;
        int y1 = y0 + 1, x1 = x0 + 1;
        bool vy0 = (unsigned)y0 < HH, vy1 = (unsigned)y1 < HH;
        bool vx0 = (unsigned)x0 < WW, vx1 = (unsigned)x1 < WW;
        float4 wv;
        wv.x = (1.f-wy)*(1.f-wx)*m * (float)(vy0 && vx0);
        wv.y = (1.f-wy)*wx      *m * (float)(vy0 && vx1);
        wv.z = wy*(1.f-wx)      *m * (float)(vy1 && vx0);
        wv.w = wy*wx            *m * (float)(vy1 && vx1);
        int yc0 = min(max(y0, 0), HH-1), yc1 = min(max(y1, 0), HH-1);
        int xc0 = min(max(x0, 0), WW-1), xc1 = min(max(x1, 0), WW-1);
        int rowb = b*HH;
        int4 iv;
        iv.x = ((rowb + yc0)*WW + xc0) * (CC/4);
        iv.y = ((rowb + yc0)*WW + xc1) * (CC/4);
        iv.z = ((rowb + yc1)*WW + xc0) * (CC/4);
        iv.w = ((rowb + yc1)*WW + xc1) * (CC/4);
        sm.sCW[q] = wv;
        sm.sCI[q] = iv;
    }
    if (t < 32) {
        int pgl = pbase + t;
        sm.sOB[t] = (pgl / HW) * (CC*HW) + (pgl % HW);
    }
    sm.sBias[t] = bias[t];
    __syncthreads();

    deform_gather(&sm, 0, 0, t);
    __syncthreads();

    float acc[8][4];
#pragma unroll
    for (int nt = 0; nt < 8; nt++)
#pragma unroll
        for (int q = 0; q < 4; q++) acc[nt][q] = 0.f;

    int m0 = wm * 16;
    int rowterm = (m0 + (lane & 15)) * 128;
    int kterm = ((lane >> 4) & 1) * 16;
    int swzl = (lane & 7) << 4;

    for (int tap = 0; tap < 9; tap++) {
        int buf = tap & 1;
        if (tap + 1 < 9) deform_gather(&sm, tap + 1, buf ^ 1, t);

#pragma unroll 1
        for (int c4 = 0; c4 < 4; c4++) {
            uint32_t Ah = sb + buf*16384 + c4*4096;
            const uint2* gbase = g_wf + ((size_t)(tap*4 + c4)*4*32 + wn*8) * 32 + lane;
#pragma unroll
            for (int h = 0; h < 4; h++) {
                uint2 bf[8];
#pragma unroll
                for (int nt = 0; nt < 8; nt++)
                    bf[nt] = gbase[(h*32 + nt) * 32];
                int off = (h*32 + kterm) ^ swzl;
                uint32_t a0, a1, a2, a3;
                ldsm4(a0, a1, a2, a3, Ah + rowterm + off);
#pragma unroll
                for (int nt = 0; nt < 8; nt++)
                    mma16816(acc[nt], a0, a1, a2, a3, bf[nt].x, bf[nt].y);
            }
        }
        __syncthreads();
    }

    // epilogue: acc -> smem (reuse A region) -> coalesced NCHW stores
    float* sEp = (float*)sm.sU;   // [o][m] = [256][32]
    int rr = lane >> 2, cc = 2*(lane & 3);
#pragma unroll
    for (int nt = 0; nt < 8; nt++) {
        int n = (wn*8 + nt)*8 + cc;
        int m = m0 + rr;
        sEp[n*32 + m]         = acc[nt][0];
        sEp[(n+1)*32 + m]     = acc[nt][1];
        sEp[n*32 + m + 8]     = acc[nt][2];
        sEp[(n+1)*32 + m + 8] = acc[nt][3];
    }
    __syncthreads();
#pragma unroll
    for (int i = 0; i < 32; i++) {
        int idx = i*256 + t;
        int m = idx & 31, o = idx >> 5;
        out[sm.sOB[m] + o*HW] = sEp[idx] + sm.sBias[o];
    }
}

// ---------------------------------------------------------------------------
extern "C" void kernel_launch(void* const* d_in, const int* in_sizes, int n_in,
                              void* d_out, int out_size) {
    const float* x     = (const float*)d_in[0];
    const float* off_w = (const float*)d_in[1];
    const float* off_b = (const float*)d_in[2];
    const float* mod_w = (const float*)d_in[3];
    const float* mod_b = (const float*)d_in[4];
    const float* w     = (const float*)d_in[5];
    const float* b     = (const float*)d_in[6];
    float* out = (float*)d_out;

    pool_h<<<(NPOS*CC)/256, 256>>>(x);
    pool_v<<<BB*HH*5*16, 256>>>();
    wprep_kernel<<<(NWF + NWFO + 255)/256, 256>>>(off_w, mod_w, w);
    offmask_kernel<<<NPOS/32, 256>>>(off_b, mod_b);
    deform_kernel<<<NPOS/32, 256>>>(b, out);
}